// round 1
// baseline (speedup 1.0000x reference)
#include <cuda_runtime.h>
#include <math.h>

#define E_EDGES 200000
#define N_N     20000
#define KSLOT   20
#define HID     100
#define TDIM    100
#define EFD     128
#define FIN     228          // EFD + TDIM
#define RH      400
#define MROWS   (N_N*KSLOT)  // 400000
#define LN_EPS  1e-5f

// scratch (device globals; no allocation allowed)
__device__ float g_split[(size_t)MROWS * HID];  // x: scatter target, colmix in-place  (160MB)
__device__ float g_y[(size_t)MROWS * HID];      // rowLN output Y, later reused as X2  (160MB)
__device__ float g_h[(size_t)MROWS * RH];       // gelu hidden                         (640MB)

__device__ __forceinline__ float gelu_f(float x) {
    return 0.5f * x * (1.0f + erff(x * 0.70710678118654752f));
}

// ---------------------------------------------------------------- K0: zero split
__global__ void k_zero() {
    size_t i = (size_t)blockIdx.x * blockDim.x + threadIdx.x;
    const size_t n4 = (size_t)MROWS * HID / 4;
    if (i < n4) ((float4*)g_split)[i] = make_float4(0.f, 0.f, 0.f, 0.f);
}

// ---------------------------------------------------------------- K1: edge MLP + scatter
// 64 edges/block, 256 threads. smem: ws[228][132] (lin_w transposed), fs[64][228], tw[100]
#define WS_STRIDE 132
#define EDGE_SMEM ((FIN*WS_STRIDE + 64*FIN + TDIM) * 4)

__global__ __launch_bounds__(256) void k_edge(
    const float* __restrict__ ef, const float* __restrict__ et,
    const int* __restrict__ nid, const int* __restrict__ idxp,
    const float* __restrict__ lw, const float* __restrict__ lb)
{
    extern __shared__ float sm1[];
    float* ws = sm1;                       // [228][132]: ws[j*132 + h]
    float* fs = ws + FIN * WS_STRIDE;      // [64][228]
    float* tw = fs + 64 * FIN;             // [100]
    int tid = threadIdx.x;
    int e0 = blockIdx.x * 64;

    for (int o = tid; o < FIN * WS_STRIDE; o += 256) ws[o] = 0.f;
    if (tid < TDIM) tw[tid] = exp10f(-(9.0f / 99.0f) * (float)tid);
    __syncthreads();

    // weights transposed: ws[j][h] = lin_w[h][j]  (coalesced read, 4-way conflict write)
    for (int o = tid; o < HID * FIN; o += 256) {
        int h = o / FIN, j = o - h * FIN;
        ws[j * WS_STRIDE + h] = lw[o];
    }
    // edge features
    for (int o = tid; o < 64 * (EFD / 4); o += 256) {
        int e = o >> 5, j4 = o & 31;
        float4 v = ((const float4*)ef)[(size_t)(e0 + e) * (EFD / 4) + j4];
        float* dst = fs + e * FIN + j4 * 4;
        dst[0] = v.x; dst[1] = v.y; dst[2] = v.z; dst[3] = v.w;
    }
    // time encoding
    for (int o = tid; o < 64 * TDIM; o += 256) {
        int e = o / TDIM, t = o - e * TDIM;
        fs[e * FIN + EFD + t] = cosf(et[e0 + e] * tw[t]);
    }
    __syncthreads();

    int ht = tid & 31;     // 32 h-threads, 4 h each -> covers 128 (mask h<100)
    int eth = tid >> 5;    // 8 e-threads, 8 edges each -> 64
    float acc[8][4];
#pragma unroll
    for (int i = 0; i < 8; i++)
#pragma unroll
        for (int j = 0; j < 4; j++) acc[i][j] = 0.f;

    const float* wp = ws + ht * 4;
    const float* fp = fs + eth * 8 * FIN;
    for (int j = 0; j < FIN; j++) {
        float4 w = *(const float4*)(wp + j * WS_STRIDE);
#pragma unroll
        for (int i = 0; i < 8; i++) {
            float f = fp[i * FIN + j];
            acc[i][0] += f * w.x; acc[i][1] += f * w.y;
            acc[i][2] += f * w.z; acc[i][3] += f * w.w;
        }
    }

    int h0 = ht * 4;
    if (h0 < HID) {
        float4 bb = *(const float4*)(lb + h0);
#pragma unroll
        for (int i = 0; i < 8; i++) {
            int e = e0 + eth * 8 + i;
            int pos = nid[e] * KSLOT + idxp[e];       // unique positions -> plain store
            float4 r = make_float4(acc[i][0] + bb.x, acc[i][1] + bb.y,
                                   acc[i][2] + bb.z, acc[i][3] + bb.w);
            *(float4*)(g_split + (size_t)pos * HID + h0) = r;
        }
    }
}

// ---------------------------------------------------------------- K2: column mixer (per node, per channel)
__global__ __launch_bounds__(256) void k_colmix(
    const float* __restrict__ cg, const float* __restrict__ cb,
    const float* __restrict__ cw1, const float* __restrict__ cb1,
    const float* __restrict__ cw2, const float* __restrict__ cb2)
{
    int gid = blockIdx.x * 256 + threadIdx.x;
    if (gid >= N_N * HID) return;
    int nn = gid / HID, c = gid - nn * HID;
    float* base = g_split + (size_t)nn * KSLOT * HID + c;

    float v[KSLOT]; float s = 0.f;
#pragma unroll
    for (int k = 0; k < KSLOT; k++) { v[k] = base[k * HID]; s += v[k]; }
    float mu = s * (1.0f / KSLOT);
    float s2 = 0.f;
#pragma unroll
    for (int k = 0; k < KSLOT; k++) { float d = v[k] - mu; s2 += d * d; }
    float rs = rsqrtf(s2 * (1.0f / KSLOT) + LN_EPS);

    float vn[KSLOT];
#pragma unroll
    for (int k = 0; k < KSLOT; k++) vn[k] = (v[k] - mu) * rs * cg[k] + cb[k];

    float h1[10];
#pragma unroll
    for (int m = 0; m < 10; m++) {
        float a = cb1[m];
#pragma unroll
        for (int k = 0; k < KSLOT; k++) a += cw1[m * KSLOT + k] * vn[k];
        h1[m] = gelu_f(a);
    }
#pragma unroll
    for (int k = 0; k < KSLOT; k++) {
        float d = cb2[k];
#pragma unroll
        for (int m = 0; m < 10; m++) d += cw2[k * 10 + m] * h1[m];
        base[k * HID] = v[k] + d;            // residual
    }
}

// ---------------------------------------------------------------- K3: row layernorm -> Y
__global__ __launch_bounds__(256) void k_rowln(const float* __restrict__ g, const float* __restrict__ b) {
    int row = (blockIdx.x * 256 + threadIdx.x) >> 5;
    int lane = threadIdx.x & 31;
    if (row >= MROWS) return;
    const float* x = g_split + (size_t)row * HID;
    float v[4]; float s = 0.f, s2 = 0.f;
#pragma unroll
    for (int i = 0; i < 4; i++) {
        int c = lane + 32 * i;
        v[i] = (c < HID) ? x[c] : 0.f;
        s += v[i]; s2 += v[i] * v[i];
    }
#pragma unroll
    for (int off = 16; off; off >>= 1) {
        s  += __shfl_xor_sync(0xffffffffu, s,  off);
        s2 += __shfl_xor_sync(0xffffffffu, s2, off);
    }
    float mu = s * 0.01f;
    float rs = rsqrtf(s2 * 0.01f - mu * mu + LN_EPS);
#pragma unroll
    for (int i = 0; i < 4; i++) {
        int c = lane + 32 * i;
        if (c < HID) g_y[(size_t)row * HID + c] = (v[i] - mu) * rs * g[c] + b[c];
    }
}

// ---------------------------------------------------------------- K4: H = gelu(Y @ W1^T + b1)   [400K,100]x[100,400]
#define GEMM_SMEM (2 * 100 * 68 * 4)

__global__ __launch_bounds__(256) void k_gemm1(const float* __restrict__ w1, const float* __restrict__ b1) {
    extern __shared__ float sm4[];
    float* As = sm4;              // As[k*68 + m]
    float* Bs = sm4 + 100 * 68;   // Bs[k*68 + n]
    int tid = threadIdx.x;
    int m0 = blockIdx.x * 64;
    int n0 = blockIdx.y * 64;

    for (int o = tid; o < 64 * 100; o += 256) {
        int r = o / 100, k = o - r * 100;
        As[k * 68 + r] = g_y[(size_t)(m0 + r) * 100 + k];
    }
    for (int o = tid; o < 64 * 100; o += 256) {
        int r = o / 100, k = o - r * 100;
        int n = n0 + r;
        Bs[k * 68 + r] = (n < RH) ? w1[n * 100 + k] : 0.f;
    }
    __syncthreads();

    int tn = tid & 15, tm = tid >> 4;
    float acc[4][4];
#pragma unroll
    for (int i = 0; i < 4; i++)
#pragma unroll
        for (int j = 0; j < 4; j++) acc[i][j] = 0.f;
    const float* Ap = As + tm * 4;
    const float* Bp = Bs + tn * 4;
#pragma unroll 2
    for (int k = 0; k < 100; k++) {
        float4 a = *(const float4*)(Ap + k * 68);
        float4 b = *(const float4*)(Bp + k * 68);
        acc[0][0] += a.x*b.x; acc[0][1] += a.x*b.y; acc[0][2] += a.x*b.z; acc[0][3] += a.x*b.w;
        acc[1][0] += a.y*b.x; acc[1][1] += a.y*b.y; acc[1][2] += a.y*b.z; acc[1][3] += a.y*b.w;
        acc[2][0] += a.z*b.x; acc[2][1] += a.z*b.y; acc[2][2] += a.z*b.z; acc[2][3] += a.z*b.w;
        acc[3][0] += a.w*b.x; acc[3][1] += a.w*b.y; acc[3][2] += a.w*b.z; acc[3][3] += a.w*b.w;
    }
    int n = n0 + tn * 4;
    if (n < RH) {
        float4 bb = *(const float4*)(b1 + n);
#pragma unroll
        for (int i = 0; i < 4; i++) {
            int m = m0 + tm * 4 + i;
            float4 r = make_float4(gelu_f(acc[i][0] + bb.x), gelu_f(acc[i][1] + bb.y),
                                   gelu_f(acc[i][2] + bb.z), gelu_f(acc[i][3] + bb.w));
            *(float4*)(g_h + (size_t)m * RH + n) = r;
        }
    }
}

// ---------------------------------------------------------------- K5: X2 = H @ W2^T + b2 + x1   [400K,400]x[400,100]
__global__ __launch_bounds__(256) void k_gemm2(const float* __restrict__ w2, const float* __restrict__ b2) {
    extern __shared__ float sm5[];
    float* As = sm5;
    float* Bs = sm5 + 100 * 68;
    int tid = threadIdx.x;
    int m0 = blockIdx.x * 64;
    int n0 = blockIdx.y * 64;
    int tn = tid & 15, tm = tid >> 4;
    float acc[4][4];
#pragma unroll
    for (int i = 0; i < 4; i++)
#pragma unroll
        for (int j = 0; j < 4; j++) acc[i][j] = 0.f;

    for (int kb = 0; kb < 4; kb++) {
        int k0 = kb * 100;
        if (kb) __syncthreads();
        for (int o = tid; o < 64 * 100; o += 256) {
            int r = o / 100, k = o - r * 100;
            As[k * 68 + r] = g_h[(size_t)(m0 + r) * RH + k0 + k];
        }
        for (int o = tid; o < 64 * 100; o += 256) {
            int r = o / 100, k = o - r * 100;
            int n = n0 + r;
            Bs[k * 68 + r] = (n < HID) ? w2[n * RH + k0 + k] : 0.f;
        }
        __syncthreads();
        const float* Ap = As + tm * 4;
        const float* Bp = Bs + tn * 4;
#pragma unroll 2
        for (int k = 0; k < 100; k++) {
            float4 a = *(const float4*)(Ap + k * 68);
            float4 b = *(const float4*)(Bp + k * 68);
            acc[0][0] += a.x*b.x; acc[0][1] += a.x*b.y; acc[0][2] += a.x*b.z; acc[0][3] += a.x*b.w;
            acc[1][0] += a.y*b.x; acc[1][1] += a.y*b.y; acc[1][2] += a.y*b.z; acc[1][3] += a.y*b.w;
            acc[2][0] += a.z*b.x; acc[2][1] += a.z*b.y; acc[2][2] += a.z*b.z; acc[2][3] += a.z*b.w;
            acc[3][0] += a.w*b.x; acc[3][1] += a.w*b.y; acc[3][2] += a.w*b.z; acc[3][3] += a.w*b.w;
        }
    }
    int n = n0 + tn * 4;
    if (n < HID) {
        float4 bb = *(const float4*)(b2 + n);
#pragma unroll
        for (int i = 0; i < 4; i++) {
            int m = m0 + tm * 4 + i;
            float4 x1 = *(const float4*)(g_split + (size_t)m * HID + n);
            float4 r = make_float4(acc[i][0] + bb.x + x1.x, acc[i][1] + bb.y + x1.y,
                                   acc[i][2] + bb.z + x1.z, acc[i][3] + bb.w + x1.w);
            *(float4*)(g_y + (size_t)m * HID + n) = r;   // X2 overwrites Y (Y fully consumed)
        }
    }
}

// ---------------------------------------------------------------- K6: final LN + mean over K + out proj
__global__ __launch_bounds__(128) void k_final(
    const float* __restrict__ ng, const float* __restrict__ nb,
    const float* __restrict__ ow, const float* __restrict__ ob,
    float* __restrict__ out)
{
    __shared__ float Mp[4][HID];
    __shared__ float Ms[HID];
    int n = blockIdx.x;
    int tid = threadIdx.x, warp = tid >> 5, lane = tid & 31;

    float psum[4] = {0.f, 0.f, 0.f, 0.f};
    for (int rr = 0; rr < 5; rr++) {
        int k = warp * 5 + rr;
        const float* x = g_y + (size_t)(n * KSLOT + k) * HID;
        float v[4]; float s = 0.f, s2 = 0.f;
#pragma unroll
        for (int i = 0; i < 4; i++) {
            int c = lane + 32 * i;
            v[i] = (c < HID) ? x[c] : 0.f;
            s += v[i]; s2 += v[i] * v[i];
        }
#pragma unroll
        for (int off = 16; off; off >>= 1) {
            s  += __shfl_xor_sync(0xffffffffu, s,  off);
            s2 += __shfl_xor_sync(0xffffffffu, s2, off);
        }
        float mu = s * 0.01f;
        float rs = rsqrtf(s2 * 0.01f - mu * mu + LN_EPS);
#pragma unroll
        for (int i = 0; i < 4; i++) {
            int c = lane + 32 * i;
            if (c < HID) psum[i] += (v[i] - mu) * rs * ng[c] + nb[c];
        }
    }
#pragma unroll
    for (int i = 0; i < 4; i++) {
        int c = lane + 32 * i;
        if (c < HID) Mp[warp][c] = psum[i];
    }
    __syncthreads();
    if (tid < HID) Ms[tid] = (Mp[0][tid] + Mp[1][tid] + Mp[2][tid] + Mp[3][tid]) * (1.0f / KSLOT);
    __syncthreads();

    for (int o = warp; o < HID; o += 4) {   // warp per output -> coalesced ow reads
        float a = 0.f;
#pragma unroll
        for (int i = 0; i < 4; i++) {
            int c = lane + 32 * i;
            if (c < HID) a += Ms[c] * ow[o * HID + c];
        }
#pragma unroll
        for (int off = 16; off; off >>= 1) a += __shfl_xor_sync(0xffffffffu, a, off);
        if (lane == 0) out[(size_t)n * HID + o] = a + ob[o];
    }
}

// ---------------------------------------------------------------- launch
extern "C" void kernel_launch(void* const* d_in, const int* in_sizes, int n_in,
                              void* d_out, int out_size)
{
    const float* ef       = (const float*)d_in[0];
    const float* et       = (const float*)d_in[1];
    const int*   nid      = (const int*)  d_in[2];
    const int*   idx      = (const int*)  d_in[3];
    const float* lin_w    = (const float*)d_in[4];
    const float* lin_b    = (const float*)d_in[5];
    const float* col_ln_g = (const float*)d_in[6];
    const float* col_ln_b = (const float*)d_in[7];
    const float* col_w1   = (const float*)d_in[8];
    const float* col_b1   = (const float*)d_in[9];
    const float* col_w2   = (const float*)d_in[10];
    const float* col_b2   = (const float*)d_in[11];
    const float* row_ln_g = (const float*)d_in[12];
    const float* row_ln_b = (const float*)d_in[13];
    const float* row_w1   = (const float*)d_in[14];
    const float* row_b1   = (const float*)d_in[15];
    const float* row_w2   = (const float*)d_in[16];
    const float* row_b2   = (const float*)d_in[17];
    const float* norm_g   = (const float*)d_in[18];
    const float* norm_b   = (const float*)d_in[19];
    const float* out_w    = (const float*)d_in[20];
    const float* out_b    = (const float*)d_in[21];
    float* out = (float*)d_out;

    cudaFuncSetAttribute((const void*)k_edge,  cudaFuncAttributeMaxDynamicSharedMemorySize, EDGE_SMEM);
    cudaFuncSetAttribute((const void*)k_gemm1, cudaFuncAttributeMaxDynamicSharedMemorySize, GEMM_SMEM);
    cudaFuncSetAttribute((const void*)k_gemm2, cudaFuncAttributeMaxDynamicSharedMemorySize, GEMM_SMEM);

    k_zero<<<(MROWS * HID / 4 + 255) / 256, 256>>>();
    k_edge<<<E_EDGES / 64, 256, EDGE_SMEM>>>(ef, et, nid, idx, lin_w, lin_b);
    k_colmix<<<(N_N * HID + 255) / 256, 256>>>(col_ln_g, col_ln_b, col_w1, col_b1, col_w2, col_b2);
    k_rowln<<<MROWS / 8, 256>>>(row_ln_g, row_ln_b);
    k_gemm1<<<dim3(MROWS / 64, 7), 256, GEMM_SMEM>>>(row_w1, row_b1);
    k_gemm2<<<dim3(MROWS / 64, 2), 256, GEMM_SMEM>>>(row_w2, row_b2);
    k_final<<<N_N, 128>>>(norm_g, norm_b, out_w, out_b, out);
}

// round 4
// speedup vs baseline: 1.3700x; 1.3700x over previous
#include <cuda_runtime.h>
#include <cuda_bf16.h>
#include <math.h>

#define E_EDGES 200000
#define N_N     20000
#define KSLOT   20
#define HID     100
#define TDIM    100
#define EFD     128
#define FIN     228          // EFD + TDIM
#define RH      400
#define MROWS   (N_N*KSLOT)  // 400000
#define LN_EPS  1e-5f

// scratch (device globals; no allocation allowed)
__device__ float g_split[(size_t)MROWS * HID];  // x: scatter target, colmix in-place, residual
__device__ float g_y[(size_t)MROWS * HID];      // mixer output X2

__device__ __forceinline__ float gelu_f(float x) {
    return 0.5f * x * (1.0f + erff(x * 0.70710678118654752f));
}

__device__ __forceinline__ unsigned f2tf(float v) {
    unsigned r;
    asm("cvt.rna.tf32.f32 %0, %1;" : "=r"(r) : "f"(v));
    return r;
}
__device__ __forceinline__ float f2tf_f(float v) { return __uint_as_float(f2tf(v)); }

// permute k within each 8-block so (c, c+4) fragment pairs are adjacent
__device__ __forceinline__ int kperm(int k) {
    return (k & ~7) | (((k & 3) << 1) | ((k >> 2) & 1));
}

// ---------------------------------------------------------------- K0: zero split
__global__ void k_zero() {
    size_t i = (size_t)blockIdx.x * blockDim.x + threadIdx.x;
    const size_t n4 = (size_t)MROWS * HID / 4;
    if (i < n4) ((float4*)g_split)[i] = make_float4(0.f, 0.f, 0.f, 0.f);
}

// ---------------------------------------------------------------- K1: edge MLP + scatter (fp32)
#define WS_STRIDE 132
#define EDGE_SMEM ((FIN*WS_STRIDE + 64*FIN + TDIM) * 4)

__global__ __launch_bounds__(256) void k_edge(
    const float* __restrict__ ef, const float* __restrict__ et,
    const int* __restrict__ nid, const int* __restrict__ idxp,
    const float* __restrict__ lw, const float* __restrict__ lb)
{
    extern __shared__ float sm1[];
    float* ws = sm1;                       // [228][132]
    float* fs = ws + FIN * WS_STRIDE;      // [64][228]
    float* tw = fs + 64 * FIN;             // [100]
    int tid = threadIdx.x;
    int e0 = blockIdx.x * 64;

    for (int o = tid; o < FIN * WS_STRIDE; o += 256) ws[o] = 0.f;
    if (tid < TDIM) tw[tid] = exp10f(-(9.0f / 99.0f) * (float)tid);
    __syncthreads();

    for (int o = tid; o < HID * FIN; o += 256) {
        int h = o / FIN, j = o - h * FIN;
        ws[j * WS_STRIDE + h] = lw[o];
    }
    for (int o = tid; o < 64 * (EFD / 4); o += 256) {
        int e = o >> 5, j4 = o & 31;
        float4 v = ((const float4*)ef)[(size_t)(e0 + e) * (EFD / 4) + j4];
        float* dst = fs + e * FIN + j4 * 4;
        dst[0] = v.x; dst[1] = v.y; dst[2] = v.z; dst[3] = v.w;
    }
    for (int o = tid; o < 64 * TDIM; o += 256) {
        int e = o / TDIM, t = o - e * TDIM;
        fs[e * FIN + EFD + t] = cosf(et[e0 + e] * tw[t]);
    }
    __syncthreads();

    int ht = tid & 31;
    int eth = tid >> 5;
    float acc[8][4];
#pragma unroll
    for (int i = 0; i < 8; i++)
#pragma unroll
        for (int j = 0; j < 4; j++) acc[i][j] = 0.f;

    const float* wp = ws + ht * 4;
    const float* fp = fs + eth * 8 * FIN;
    for (int j = 0; j < FIN; j++) {
        float4 w = *(const float4*)(wp + j * WS_STRIDE);
#pragma unroll
        for (int i = 0; i < 8; i++) {
            float f = fp[i * FIN + j];
            acc[i][0] += f * w.x; acc[i][1] += f * w.y;
            acc[i][2] += f * w.z; acc[i][3] += f * w.w;
        }
    }

    int h0 = ht * 4;
    if (h0 < HID) {
        float4 bb = *(const float4*)(lb + h0);
#pragma unroll
        for (int i = 0; i < 8; i++) {
            int e = e0 + eth * 8 + i;
            int pos = nid[e] * KSLOT + idxp[e];
            float4 r = make_float4(acc[i][0] + bb.x, acc[i][1] + bb.y,
                                   acc[i][2] + bb.z, acc[i][3] + bb.w);
            *(float4*)(g_split + (size_t)pos * HID + h0) = r;
        }
    }
}

// ---------------------------------------------------------------- K2: column mixer (fp32)
__global__ __launch_bounds__(256) void k_colmix(
    const float* __restrict__ cg, const float* __restrict__ cb,
    const float* __restrict__ cw1, const float* __restrict__ cb1,
    const float* __restrict__ cw2, const float* __restrict__ cb2)
{
    int gid = blockIdx.x * 256 + threadIdx.x;
    if (gid >= N_N * HID) return;
    int nn = gid / HID, c = gid - nn * HID;
    float* base = g_split + (size_t)nn * KSLOT * HID + c;

    float v[KSLOT]; float s = 0.f;
#pragma unroll
    for (int k = 0; k < KSLOT; k++) { v[k] = base[k * HID]; s += v[k]; }
    float mu = s * (1.0f / KSLOT);
    float s2 = 0.f;
#pragma unroll
    for (int k = 0; k < KSLOT; k++) { float d = v[k] - mu; s2 += d * d; }
    float rs = rsqrtf(s2 * (1.0f / KSLOT) + LN_EPS);

    float vn[KSLOT];
#pragma unroll
    for (int k = 0; k < KSLOT; k++) vn[k] = (v[k] - mu) * rs * cg[k] + cb[k];

    float h1[10];
#pragma unroll
    for (int m = 0; m < 10; m++) {
        float a = cb1[m];
#pragma unroll
        for (int k = 0; k < KSLOT; k++) a += cw1[m * KSLOT + k] * vn[k];
        h1[m] = gelu_f(a);
    }
#pragma unroll
    for (int k = 0; k < KSLOT; k++) {
        float d = cb2[k];
#pragma unroll
        for (int m = 0; m < 10; m++) d += cw2[k * 10 + m] * h1[m];
        base[k * HID] = v[k] + d;
    }
}

// ---------------------------------------------------------------- K3: fused row mixer (tf32 tensor cores)
// X2 = x + gelu(LN(x) @ W1^T + b1) @ W2^T + b2   for 128 rows per block.
#define SA 116    // Yn / W1s float k-stride (112 + 4; ≡20 mod 32 -> conflict-free)
#define SH 84     // Hs / W2s float k-stride (64 + 20; ≡20 mod 32)
#define K1P 112   // padded LN-K (14 k8 steps)
#define NCH 64    // hidden chunk
#define NCHUNK 7  // 448 = 7*64 padded hidden
#define N2P 104   // padded output cols (13 n-tiles)

#define MIX_SMEM ((128*SA + 64*SA + 128*SH + N2P*SH) * 4 + 448 * 4)

#define MMA_TF32(c,a0,a1,a2,a3,b0,b1) \
    asm volatile("mma.sync.aligned.m16n8k8.row.col.f32.tf32.tf32.f32 " \
        "{%0,%1,%2,%3}, {%4,%5,%6,%7}, {%8,%9}, {%0,%1,%2,%3};" \
        : "+f"(c[0]),"+f"(c[1]),"+f"(c[2]),"+f"(c[3]) \
        : "r"(a0),"r"(a1),"r"(a2),"r"(a3),"r"(b0),"r"(b1))

__global__ __launch_bounds__(256, 1) void k_mixer(
    const float* __restrict__ lng, const float* __restrict__ lnb,
    const float* __restrict__ w1, const float* __restrict__ b1,
    const float* __restrict__ w2, const float* __restrict__ b2)
{
    extern __shared__ float smx[];
    float* Yn  = smx;                 // [128][SA]
    float* W1s = Yn  + 128 * SA;      // [64][SA]
    float* Hs  = W1s + 64 * SA;       // [128][SH]
    float* W2s = Hs  + 128 * SH;      // [N2P][SH]
    float* b1s = W2s + N2P * SH;      // [448]

    int tid  = threadIdx.x;
    int warp = tid >> 5, lane = tid & 31;
    int m0   = warp * 16;
    int q = lane >> 2, p = lane & 3;          // groupID / threadID_in_group
    size_t rowBase = (size_t)blockIdx.x * 128;

    for (int i = tid; i < 448; i += 256) b1s[i] = (i < RH) ? b1[i] : 0.f;

    // ---- rowLN -> Yn (tf32-rounded, k-permuted, zero-padded cols 100..111) ----
    for (int rr = 0; rr < 16; rr++) {
        int row = m0 + rr;
        const float* x = g_split + (rowBase + row) * HID;
        float v[4]; float s = 0.f, s2 = 0.f;
#pragma unroll
        for (int i = 0; i < 4; i++) {
            int c = lane + 32 * i;
            v[i] = (c < HID) ? x[c] : 0.f;
            s += v[i]; s2 += v[i] * v[i];
        }
#pragma unroll
        for (int off = 16; off; off >>= 1) {
            s  += __shfl_xor_sync(0xffffffffu, s,  off);
            s2 += __shfl_xor_sync(0xffffffffu, s2, off);
        }
        float mu = s * 0.01f;
        float rs = rsqrtf(s2 * 0.01f - mu * mu + LN_EPS);
#pragma unroll
        for (int i = 0; i < 4; i++) {
            int c = lane + 32 * i;
            if (c < HID)
                Yn[row * SA + kperm(c)] =
                    f2tf_f((v[i] - mu) * rs * __ldg(lng + c) + __ldg(lnb + c));
        }
        if (lane < K1P - HID) Yn[row * SA + kperm(HID + lane)] = 0.f;
    }

    float acc2[13][4];
#pragma unroll
    for (int i = 0; i < 13; i++)
#pragma unroll
        for (int j = 0; j < 4; j++) acc2[i][j] = 0.f;

    for (int ch = 0; ch < NCHUNK; ch++) {
        __syncthreads();   // protect W1s/W2s overwrite vs previous chunk's mma reads

        // ---- stage W1 chunk [64][112] (k-permuted, tf32) ----
        for (int o = tid; o < NCH * K1P; o += 256) {
            int nl = o / K1P, k = o - nl * K1P;
            int ng = ch * NCH + nl;
            W1s[nl * SA + kperm(k)] =
                f2tf_f((ng < RH && k < HID) ? w1[ng * HID + k] : 0.f);
        }
        // ---- stage W2 chunk [104][64] ----
        for (int o = tid; o < N2P * NCH; o += 256) {
            int n = o / NCH, k = o - n * NCH;
            int hg = ch * NCH + k;
            W2s[n * SH + kperm(k)] =
                f2tf_f((n < HID && hg < RH) ? w2[n * RH + hg] : 0.f);
        }
        __syncthreads();

        // ---- GEMM1: Hacc[16][64] = Yn[m0..m0+16) @ W1s^T ----
        float acc1[8][4];
#pragma unroll
        for (int i = 0; i < 8; i++)
#pragma unroll
            for (int j = 0; j < 4; j++) acc1[i][j] = 0.f;

#pragma unroll
        for (int ks = 0; ks < 14; ks++) {
            float2 alo = *(const float2*)(Yn + (m0 + q) * SA + ks * 8 + 2 * p);
            float2 ahi = *(const float2*)(Yn + (m0 + q + 8) * SA + ks * 8 + 2 * p);
            unsigned a0 = __float_as_uint(alo.x), a1 = __float_as_uint(ahi.x);
            unsigned a2 = __float_as_uint(alo.y), a3 = __float_as_uint(ahi.y);
#pragma unroll
            for (int nt = 0; nt < 8; nt++) {
                float2 bv = *(const float2*)(W1s + (nt * 8 + q) * SA + ks * 8 + 2 * p);
                MMA_TF32(acc1[nt], a0, a1, a2, a3,
                         __float_as_uint(bv.x), __float_as_uint(bv.y));
            }
        }

        // ---- bias + gelu -> Hs (tf32, k-permuted), own-warp rows only ----
        {
            int pos0 = ((2 * p & 3) << 1) | (p >> 1);   // kperm8(2p)
#pragma unroll
            for (int nt = 0; nt < 8; nt++) {
                int nl = nt * 8 + 2 * p;
                float bb0 = b1s[ch * NCH + nl], bb1 = b1s[ch * NCH + nl + 1];
                float* h0 = Hs + (m0 + q) * SH + nt * 8;
                float* h1 = Hs + (m0 + q + 8) * SH + nt * 8;
                h0[pos0]     = f2tf_f(gelu_f(acc1[nt][0] + bb0));
                h0[pos0 + 2] = f2tf_f(gelu_f(acc1[nt][1] + bb1));
                h1[pos0]     = f2tf_f(gelu_f(acc1[nt][2] + bb0));
                h1[pos0 + 2] = f2tf_f(gelu_f(acc1[nt][3] + bb1));
            }
        }
        __syncwarp();

        // ---- GEMM2 accumulate: acc2 += Hs[m0..16)[0..64) @ W2s^T ----
#pragma unroll
        for (int ks = 0; ks < 8; ks++) {
            float2 alo = *(const float2*)(Hs + (m0 + q) * SH + ks * 8 + 2 * p);
            float2 ahi = *(const float2*)(Hs + (m0 + q + 8) * SH + ks * 8 + 2 * p);
            unsigned a0 = __float_as_uint(alo.x), a1 = __float_as_uint(ahi.x);
            unsigned a2 = __float_as_uint(alo.y), a3 = __float_as_uint(ahi.y);
#pragma unroll
            for (int nt = 0; nt < 13; nt++) {
                float2 bv = *(const float2*)(W2s + (nt * 8 + q) * SH + ks * 8 + 2 * p);
                MMA_TF32(acc2[nt], a0, a1, a2, a3,
                         __float_as_uint(bv.x), __float_as_uint(bv.y));
            }
        }
    }

    // ---- epilogue: + b2 + residual -> g_y (fp32) ----
#pragma unroll
    for (int nt = 0; nt < 13; nt++) {
        int col = nt * 8 + 2 * p;
        if (col < HID) {
            float bb0 = __ldg(b2 + col), bb1 = __ldg(b2 + col + 1);
            size_t r0 = rowBase + m0 + q, r1 = r0 + 8;
            float2 x0 = *(const float2*)(g_split + r0 * HID + col);
            float2 x1 = *(const float2*)(g_split + r1 * HID + col);
            float2 o0 = make_float2(acc2[nt][0] + bb0 + x0.x, acc2[nt][1] + bb1 + x0.y);
            float2 o1 = make_float2(acc2[nt][2] + bb0 + x1.x, acc2[nt][3] + bb1 + x1.y);
            *(float2*)(g_y + r0 * HID + col) = o0;
            *(float2*)(g_y + r1 * HID + col) = o1;
        }
    }
}

// ---------------------------------------------------------------- K4: final LN + mean over K + out proj
__global__ __launch_bounds__(128) void k_final(
    const float* __restrict__ ng, const float* __restrict__ nb,
    const float* __restrict__ ow, const float* __restrict__ ob,
    float* __restrict__ out)
{
    __shared__ float Mp[4][HID];
    __shared__ float Ms[HID];
    int n = blockIdx.x;
    int tid = threadIdx.x, warp = tid >> 5, lane = tid & 31;

    float psum[4] = {0.f, 0.f, 0.f, 0.f};
    for (int rr = 0; rr < 5; rr++) {
        int k = warp * 5 + rr;
        const float* x = g_y + (size_t)(n * KSLOT + k) * HID;
        float v[4]; float s = 0.f, s2 = 0.f;
#pragma unroll
        for (int i = 0; i < 4; i++) {
            int c = lane + 32 * i;
            v[i] = (c < HID) ? x[c] : 0.f;
            s += v[i]; s2 += v[i] * v[i];
        }
#pragma unroll
        for (int off = 16; off; off >>= 1) {
            s  += __shfl_xor_sync(0xffffffffu, s,  off);
            s2 += __shfl_xor_sync(0xffffffffu, s2, off);
        }
        float mu = s * 0.01f;
        float rs = rsqrtf(s2 * 0.01f - mu * mu + LN_EPS);
#pragma unroll
        for (int i = 0; i < 4; i++) {
            int c = lane + 32 * i;
            if (c < HID) psum[i] += (v[i] - mu) * rs * ng[c] + nb[c];
        }
    }
#pragma unroll
    for (int i = 0; i < 4; i++) {
        int c = lane + 32 * i;
        if (c < HID) Mp[warp][c] = psum[i];
    }
    __syncthreads();
    if (tid < HID) Ms[tid] = (Mp[0][tid] + Mp[1][tid] + Mp[2][tid] + Mp[3][tid]) * (1.0f / KSLOT);
    __syncthreads();

    for (int o = warp; o < HID; o += 4) {
        float a = 0.f;
#pragma unroll
        for (int i = 0; i < 4; i++) {
            int c = lane + 32 * i;
            if (c < HID) a += Ms[c] * ow[o * HID + c];
        }
#pragma unroll
        for (int off = 16; off; off >>= 1) a += __shfl_xor_sync(0xffffffffu, a, off);
        if (lane == 0) out[(size_t)n * HID + o] = a + ob[o];
    }
}

// ---------------------------------------------------------------- launch
extern "C" void kernel_launch(void* const* d_in, const int* in_sizes, int n_in,
                              void* d_out, int out_size)
{
    const float* ef       = (const float*)d_in[0];
    const float* et       = (const float*)d_in[1];
    const int*   nid      = (const int*)  d_in[2];
    const int*   idx      = (const int*)  d_in[3];
    const float* lin_w    = (const float*)d_in[4];
    const float* lin_b    = (const float*)d_in[5];
    const float* col_ln_g = (const float*)d_in[6];
    const float* col_ln_b = (const float*)d_in[7];
    const float* col_w1   = (const float*)d_in[8];
    const float* col_b1   = (const float*)d_in[9];
    const float* col_w2   = (const float*)d_in[10];
    const float* col_b2   = (const float*)d_in[11];
    const float* row_ln_g = (const float*)d_in[12];
    const float* row_ln_b = (const float*)d_in[13];
    const float* row_w1   = (const float*)d_in[14];
    const float* row_b1   = (const float*)d_in[15];
    const float* row_w2   = (const float*)d_in[16];
    const float* row_b2   = (const float*)d_in[17];
    const float* norm_g   = (const float*)d_in[18];
    const float* norm_b   = (const float*)d_in[19];
    const float* out_w    = (const float*)d_in[20];
    const float* out_b    = (const float*)d_in[21];
    float* out = (float*)d_out;

    cudaFuncSetAttribute((const void*)k_edge,  cudaFuncAttributeMaxDynamicSharedMemorySize, EDGE_SMEM);
    cudaFuncSetAttribute((const void*)k_mixer, cudaFuncAttributeMaxDynamicSharedMemorySize, MIX_SMEM);

    k_zero<<<(MROWS * HID / 4 + 255) / 256, 256>>>();
    k_edge<<<E_EDGES / 64, 256, EDGE_SMEM>>>(ef, et, nid, idx, lin_w, lin_b);
    k_colmix<<<(N_N * HID + 255) / 256, 256>>>(col_ln_g, col_ln_b, col_w1, col_b1, col_w2, col_b2);
    k_mixer<<<MROWS / 128, 256, MIX_SMEM>>>(row_ln_g, row_ln_b, row_w1, row_b1, row_w2, row_b2);
    k_final<<<N_N, 128>>>(norm_g, norm_b, out_w, out_b, out);
}

// round 5
// speedup vs baseline: 1.7340x; 1.2657x over previous
#include <cuda_runtime.h>
#include <cuda_bf16.h>
#include <math.h>

#define E_EDGES 200000
#define N_N     20000
#define KSLOT   20
#define HID     100
#define TDIM    100
#define EFD     128
#define FIN     228          // EFD + TDIM
#define RH      400
#define MROWS   (N_N*KSLOT)  // 400000
#define LN_EPS  1e-5f

// scratch (device globals; no allocation allowed)
__device__ float g_split[(size_t)MROWS * HID];  // x: scatter target, colmix in-place, residual
__device__ float g_y[(size_t)MROWS * HID];      // mixer output X2
__device__ float g_w1p[448 * 112];              // tf32-rounded, perm16 W1 [448][112]
__device__ float g_w2p[14 * 104 * 32];          // tf32-rounded, perm16 W2 chunks [14][104][32]

__device__ __forceinline__ float gelu_f(float x) {
    return 0.5f * x * (1.0f + erff(x * 0.70710678118654752f));
}

__device__ __forceinline__ unsigned f2tf(float v) {
    unsigned r;
    asm("cvt.rna.tf32.f32 %0, %1;" : "=r"(r) : "f"(v));
    return r;
}
__device__ __forceinline__ float f2tf_f(float v) { return __uint_as_float(f2tf(v)); }

// permute k within each 16-block: thread p's 4 frag elems (k = p, p+4, p+8, p+12) contiguous
__device__ __forceinline__ int kperm16(int k) {
    return (k & ~15) | (((k & 3) << 2) | ((k >> 2) & 3));
}

// ---------------------------------------------------------------- K0: zero split
__global__ void k_zero() {
    size_t i = (size_t)blockIdx.x * blockDim.x + threadIdx.x;
    const size_t n4 = (size_t)MROWS * HID / 4;
    if (i < n4) ((float4*)g_split)[i] = make_float4(0.f, 0.f, 0.f, 0.f);
}

// ---------------------------------------------------------------- K0b: prep weights (tf32 + perm16)
__global__ void k_prep(const float* __restrict__ w1, const float* __restrict__ w2) {
    int i = blockIdx.x * 256 + threadIdx.x;
    if (i < 448 * 112) {
        int ng = i / 112, k = i - ng * 112;
        g_w1p[ng * 112 + kperm16(k)] =
            f2tf_f((ng < RH && k < HID) ? w1[ng * HID + k] : 0.f);
    }
    if (i < 14 * 104 * 32) {
        int ch = i / (104 * 32);
        int r  = i - ch * 104 * 32;
        int n  = r >> 5, k = r & 31;
        g_w2p[(ch * 104 + n) * 32 + kperm16(k)] =
            f2tf_f((n < HID) ? w2[n * RH + ch * 32 + k] : 0.f);
    }
}

// ---------------------------------------------------------------- K1: edge MLP + scatter (fp32)
#define WS_STRIDE 132
#define EDGE_SMEM ((FIN*WS_STRIDE + 64*FIN + TDIM) * 4)

__global__ __launch_bounds__(256) void k_edge(
    const float* __restrict__ ef, const float* __restrict__ et,
    const int* __restrict__ nid, const int* __restrict__ idxp,
    const float* __restrict__ lw, const float* __restrict__ lb)
{
    extern __shared__ float sm1[];
    float* ws = sm1;                       // [228][132]
    float* fs = ws + FIN * WS_STRIDE;      // [64][228]
    float* tw = fs + 64 * FIN;             // [100]
    int tid = threadIdx.x;
    int e0 = blockIdx.x * 64;

    for (int o = tid; o < FIN * WS_STRIDE; o += 256) ws[o] = 0.f;
    if (tid < TDIM) tw[tid] = exp10f(-(9.0f / 99.0f) * (float)tid);
    __syncthreads();

    for (int o = tid; o < HID * FIN; o += 256) {
        int h = o / FIN, j = o - h * FIN;
        ws[j * WS_STRIDE + h] = lw[o];
    }
    for (int o = tid; o < 64 * (EFD / 4); o += 256) {
        int e = o >> 5, j4 = o & 31;
        float4 v = ((const float4*)ef)[(size_t)(e0 + e) * (EFD / 4) + j4];
        float* dst = fs + e * FIN + j4 * 4;
        dst[0] = v.x; dst[1] = v.y; dst[2] = v.z; dst[3] = v.w;
    }
    for (int o = tid; o < 64 * TDIM; o += 256) {
        int e = o / TDIM, t = o - e * TDIM;
        fs[e * FIN + EFD + t] = cosf(et[e0 + e] * tw[t]);
    }
    __syncthreads();

    int ht = tid & 31;
    int eth = tid >> 5;
    float acc[8][4];
#pragma unroll
    for (int i = 0; i < 8; i++)
#pragma unroll
        for (int j = 0; j < 4; j++) acc[i][j] = 0.f;

    const float* wp = ws + ht * 4;
    const float* fp = fs + eth * 8 * FIN;
    for (int j = 0; j < FIN; j++) {
        float4 w = *(const float4*)(wp + j * WS_STRIDE);
#pragma unroll
        for (int i = 0; i < 8; i++) {
            float f = fp[i * FIN + j];
            acc[i][0] += f * w.x; acc[i][1] += f * w.y;
            acc[i][2] += f * w.z; acc[i][3] += f * w.w;
        }
    }

    int h0 = ht * 4;
    if (h0 < HID) {
        float4 bb = *(const float4*)(lb + h0);
#pragma unroll
        for (int i = 0; i < 8; i++) {
            int e = e0 + eth * 8 + i;
            int pos = nid[e] * KSLOT + idxp[e];
            float4 r = make_float4(acc[i][0] + bb.x, acc[i][1] + bb.y,
                                   acc[i][2] + bb.z, acc[i][3] + bb.w);
            *(float4*)(g_split + (size_t)pos * HID + h0) = r;
        }
    }
}

// ---------------------------------------------------------------- K2: column mixer (fp32)
__global__ __launch_bounds__(256) void k_colmix(
    const float* __restrict__ cg, const float* __restrict__ cb,
    const float* __restrict__ cw1, const float* __restrict__ cb1,
    const float* __restrict__ cw2, const float* __restrict__ cb2)
{
    int gid = blockIdx.x * 256 + threadIdx.x;
    if (gid >= N_N * HID) return;
    int nn = gid / HID, c = gid - nn * HID;
    float* base = g_split + (size_t)nn * KSLOT * HID + c;

    float v[KSLOT]; float s = 0.f;
#pragma unroll
    for (int k = 0; k < KSLOT; k++) { v[k] = base[k * HID]; s += v[k]; }
    float mu = s * (1.0f / KSLOT);
    float s2 = 0.f;
#pragma unroll
    for (int k = 0; k < KSLOT; k++) { float d = v[k] - mu; s2 += d * d; }
    float rs = rsqrtf(s2 * (1.0f / KSLOT) + LN_EPS);

    float vn[KSLOT];
#pragma unroll
    for (int k = 0; k < KSLOT; k++) vn[k] = (v[k] - mu) * rs * cg[k] + cb[k];

    float h1[10];
#pragma unroll
    for (int m = 0; m < 10; m++) {
        float a = cb1[m];
#pragma unroll
        for (int k = 0; k < KSLOT; k++) a += cw1[m * KSLOT + k] * vn[k];
        h1[m] = gelu_f(a);
    }
#pragma unroll
    for (int k = 0; k < KSLOT; k++) {
        float d = cb2[k];
#pragma unroll
        for (int m = 0; m < 10; m++) d += cw2[k * 10 + m] * h1[m];
        base[k * HID] = v[k] + d;
    }
}

// ---------------------------------------------------------------- K3: fused row mixer (tf32 mma, LDS.128 frags)
// 64 rows/block, 128 threads: 4 warps = 2 row-groups (32 rows, M=32/warp) x 2 n-halves.
#define SA 112    // Yn/W1s stride (== extent; 112 mod 32 = 16 -> LDS.128 conflict-free)
#define SH 48     // Hs/W2s stride (k extent 32; 48 mod 32 = 16)
#define NCH 32    // hidden chunk
#define NCHUNK 14 // 448 = 14*32
#define MIX_SMEM ((64*SA + NCH*SA + 64*SH + 104*SH) * 4)   // 75264 B

#define MMA_TF32(c,a0,a1,a2,a3,b0,b1) \
    asm volatile("mma.sync.aligned.m16n8k8.row.col.f32.tf32.tf32.f32 " \
        "{%0,%1,%2,%3}, {%4,%5,%6,%7}, {%8,%9}, {%0,%1,%2,%3};" \
        : "+f"(c[0]),"+f"(c[1]),"+f"(c[2]),"+f"(c[3]) \
        : "r"(a0),"r"(a1),"r"(a2),"r"(a3),"r"(b0),"r"(b1))

__global__ __launch_bounds__(128, 3) void k_mixer(
    const float* __restrict__ lng, const float* __restrict__ lnb,
    const float* __restrict__ b1, const float* __restrict__ b2)
{
    extern __shared__ float smx[];
    float* Yn  = smx;                 // [64][SA]
    float* W1s = Yn  + 64 * SA;       // [NCH][SA]
    float* Hs  = W1s + NCH * SA;      // [64][SH]
    float* W2s = Hs  + 64 * SH;       // [104][SH]

    int tid  = threadIdx.x;
    int warp = tid >> 5, lane = tid & 31;
    int q = lane >> 2, p = lane & 3;
    int mgrp = warp & 1;              // row group (32 rows)
    int h    = warp >> 1;             // n-half
    int m0   = mgrp * 32;
    size_t rowBase = (size_t)blockIdx.x * 64;

    // ---- rowLN -> Yn (tf32-rounded, perm16, zero-padded cols 100..111) ----
    for (int rr = 0; rr < 16; rr++) {
        int row = warp * 16 + rr;
        const float* x = g_split + (rowBase + row) * HID;
        float v[4]; float s = 0.f, s2 = 0.f;
#pragma unroll
        for (int i = 0; i < 4; i++) {
            int c = lane + 32 * i;
            v[i] = (c < HID) ? x[c] : 0.f;
            s += v[i]; s2 += v[i] * v[i];
        }
#pragma unroll
        for (int off = 16; off; off >>= 1) {
            s  += __shfl_xor_sync(0xffffffffu, s,  off);
            s2 += __shfl_xor_sync(0xffffffffu, s2, off);
        }
        float mu = s * 0.01f;
        float rs = rsqrtf(s2 * 0.01f - mu * mu + LN_EPS);
#pragma unroll
        for (int i = 0; i < 4; i++) {
            int c = lane + 32 * i;
            if (c < HID)
                Yn[row * SA + kperm16(c)] =
                    f2tf_f((v[i] - mu) * rs * __ldg(lng + c) + __ldg(lnb + c));
        }
        if (lane < SA - HID) Yn[row * SA + kperm16(HID + lane)] = 0.f;
    }

    float acc2[7][4];
#pragma unroll
    for (int i = 0; i < 7; i++)
#pragma unroll
        for (int j = 0; j < 4; j++) acc2[i][j] = 0.f;
    // acc2 covers 2 m-tiles: [nt][0..1] rows m0+q(+8) of tile0... layout:
    // use two sets: accA (m-tile 0), accB (m-tile 1)
    float acc2b[7][4];
#pragma unroll
    for (int i = 0; i < 7; i++)
#pragma unroll
        for (int j = 0; j < 4; j++) acc2b[i][j] = 0.f;

    for (int ch = 0; ch < NCHUNK; ch++) {
        __syncthreads();   // prior chunk's mma reads done before staging overwrite

        // ---- stage W1 chunk [32][112] (pure copy; layout matches) ----
        {
            const float4* src = (const float4*)(g_w1p + ch * NCH * SA);
            float4* dst = (float4*)W1s;
            for (int o = tid; o < NCH * SA / 4; o += 128) dst[o] = src[o];
        }
        // ---- stage W2 chunk [104][32] -> stride 48 ----
        {
            const float4* src = (const float4*)(g_w2p + ch * 104 * 32);
            for (int o = tid; o < 104 * 8; o += 128) {
                int n = o >> 3, r = o & 7;
                *(float4*)(W2s + n * SH + r * 4) = src[o];
            }
        }
        __syncthreads();

        // ---- GEMM1: H[m0..m0+32)[h*16..h*16+16) ----
        float acc1[2][2][4];
#pragma unroll
        for (int mt = 0; mt < 2; mt++)
#pragma unroll
            for (int nt = 0; nt < 2; nt++)
#pragma unroll
                for (int j = 0; j < 4; j++) acc1[mt][nt][j] = 0.f;

#pragma unroll
        for (int ks = 0; ks < 7; ks++) {          // 7 x k16
            float4 a[2][2];
#pragma unroll
            for (int mt = 0; mt < 2; mt++) {
                a[mt][0] = *(const float4*)(Yn + (m0 + mt * 16 + q) * SA + ks * 16 + 4 * p);
                a[mt][1] = *(const float4*)(Yn + (m0 + mt * 16 + q + 8) * SA + ks * 16 + 4 * p);
            }
            float4 bv[2];
#pragma unroll
            for (int nt = 0; nt < 2; nt++)
                bv[nt] = *(const float4*)(W1s + (h * 16 + nt * 8 + q) * SA + ks * 16 + 4 * p);
#pragma unroll
            for (int mt = 0; mt < 2; mt++)
#pragma unroll
                for (int nt = 0; nt < 2; nt++) {
                    MMA_TF32(acc1[mt][nt],
                             __float_as_uint(a[mt][0].x), __float_as_uint(a[mt][1].x),
                             __float_as_uint(a[mt][0].y), __float_as_uint(a[mt][1].y),
                             __float_as_uint(bv[nt].x), __float_as_uint(bv[nt].y));
                    MMA_TF32(acc1[mt][nt],
                             __float_as_uint(a[mt][0].z), __float_as_uint(a[mt][1].z),
                             __float_as_uint(a[mt][0].w), __float_as_uint(a[mt][1].w),
                             __float_as_uint(bv[nt].z), __float_as_uint(bv[nt].w));
                }
        }

        // ---- bias + gelu -> Hs (tf32, perm16 within 16-blocks) ----
#pragma unroll
        for (int nt = 0; nt < 2; nt++) {
            int cg0 = ch * NCH + h * 16 + nt * 8 + 2 * p;     // global hidden index
            float bb0 = (cg0     < RH) ? __ldg(b1 + cg0)     : 0.f;
            float bb1 = (cg0 + 1 < RH) ? __ldg(b1 + cg0 + 1) : 0.f;
            int pos0 = h * 16 + 8 * (p & 1) + 2 * nt + (p >> 1);
#pragma unroll
            for (int mt = 0; mt < 2; mt++) {
                float* h0 = Hs + (m0 + mt * 16 + q) * SH;
                float* h1 = Hs + (m0 + mt * 16 + q + 8) * SH;
                h0[pos0]     = f2tf_f(gelu_f(acc1[mt][nt][0] + bb0));
                h0[pos0 + 4] = f2tf_f(gelu_f(acc1[mt][nt][1] + bb1));
                h1[pos0]     = f2tf_f(gelu_f(acc1[mt][nt][2] + bb0));
                h1[pos0 + 4] = f2tf_f(gelu_f(acc1[mt][nt][3] + bb1));
            }
        }
        __syncthreads();   // cross-warp: GEMM2 needs both n-halves' H cols

        // ---- GEMM2 accumulate: X2[m0..+32)[half h] += Hchunk @ W2chunk^T ----
#pragma unroll
        for (int ks = 0; ks < 2; ks++) {          // 2 x k16
            float4 a[2][2];
#pragma unroll
            for (int mt = 0; mt < 2; mt++) {
                a[mt][0] = *(const float4*)(Hs + (m0 + mt * 16 + q) * SH + ks * 16 + 4 * p);
                a[mt][1] = *(const float4*)(Hs + (m0 + mt * 16 + q + 8) * SH + ks * 16 + 4 * p);
            }
#pragma unroll
            for (int nt = 0; nt < 7; nt++) {
                int tile = h * 7 + nt;
                if (tile < 13) {
                    float4 bv = *(const float4*)(W2s + (tile * 8 + q) * SH + ks * 16 + 4 * p);
                    MMA_TF32(acc2[nt],
                             __float_as_uint(a[0][0].x), __float_as_uint(a[0][1].x),
                             __float_as_uint(a[0][0].y), __float_as_uint(a[0][1].y),
                             __float_as_uint(bv.x), __float_as_uint(bv.y));
                    MMA_TF32(acc2[nt],
                             __float_as_uint(a[0][0].z), __float_as_uint(a[0][1].z),
                             __float_as_uint(a[0][0].w), __float_as_uint(a[0][1].w),
                             __float_as_uint(bv.z), __float_as_uint(bv.w));
                    MMA_TF32(acc2b[nt],
                             __float_as_uint(a[1][0].x), __float_as_uint(a[1][1].x),
                             __float_as_uint(a[1][0].y), __float_as_uint(a[1][1].y),
                             __float_as_uint(bv.x), __float_as_uint(bv.y));
                    MMA_TF32(acc2b[nt],
                             __float_as_uint(a[1][0].z), __float_as_uint(a[1][1].z),
                             __float_as_uint(a[1][0].w), __float_as_uint(a[1][1].w),
                             __float_as_uint(bv.z), __float_as_uint(bv.w));
                }
            }
        }
    }

    // ---- epilogue: + b2 + residual -> g_y (fp32) ----
#pragma unroll
    for (int nt = 0; nt < 7; nt++) {
        int tile = h * 7 + nt;
        if (tile < 13) {
            int col = tile * 8 + 2 * p;
            if (col < HID) {
                float bb0 = __ldg(b2 + col), bb1 = __ldg(b2 + col + 1);
#pragma unroll
                for (int mt = 0; mt < 2; mt++) {
                    float (*ac)[4] = mt ? acc2b : acc2;
                    size_t r0 = rowBase + m0 + mt * 16 + q, r1 = r0 + 8;
                    float2 x0 = *(const float2*)(g_split + r0 * HID + col);
                    float2 x1 = *(const float2*)(g_split + r1 * HID + col);
                    float2 o0 = make_float2(ac[nt][0] + bb0 + x0.x, ac[nt][1] + bb1 + x0.y);
                    float2 o1 = make_float2(ac[nt][2] + bb0 + x1.x, ac[nt][3] + bb1 + x1.y);
                    *(float2*)(g_y + r0 * HID + col) = o0;
                    *(float2*)(g_y + r1 * HID + col) = o1;
                }
            }
        }
    }
}

// ---------------------------------------------------------------- K4: final LN + mean over K + out proj
__global__ __launch_bounds__(128) void k_final(
    const float* __restrict__ ng, const float* __restrict__ nb,
    const float* __restrict__ ow, const float* __restrict__ ob,
    float* __restrict__ out)
{
    __shared__ float Mp[4][HID];
    __shared__ float Ms[HID];
    int n = blockIdx.x;
    int tid = threadIdx.x, warp = tid >> 5, lane = tid & 31;

    float psum[4] = {0.f, 0.f, 0.f, 0.f};
    for (int rr = 0; rr < 5; rr++) {
        int k = warp * 5 + rr;
        const float* x = g_y + (size_t)(n * KSLOT + k) * HID;
        float v[4]; float s = 0.f, s2 = 0.f;
#pragma unroll
        for (int i = 0; i < 4; i++) {
            int c = lane + 32 * i;
            v[i] = (c < HID) ? x[c] : 0.f;
            s += v[i]; s2 += v[i] * v[i];
        }
#pragma unroll
        for (int off = 16; off; off >>= 1) {
            s  += __shfl_xor_sync(0xffffffffu, s,  off);
            s2 += __shfl_xor_sync(0xffffffffu, s2, off);
        }
        float mu = s * 0.01f;
        float rs = rsqrtf(s2 * 0.01f - mu * mu + LN_EPS);
#pragma unroll
        for (int i = 0; i < 4; i++) {
            int c = lane + 32 * i;
            if (c < HID) psum[i] += (v[i] - mu) * rs * ng[c] + nb[c];
        }
    }
#pragma unroll
    for (int i = 0; i < 4; i++) {
        int c = lane + 32 * i;
        if (c < HID) Mp[warp][c] = psum[i];
    }
    __syncthreads();
    if (tid < HID) Ms[tid] = (Mp[0][tid] + Mp[1][tid] + Mp[2][tid] + Mp[3][tid]) * (1.0f / KSLOT);
    __syncthreads();

    for (int o = warp; o < HID; o += 4) {
        float a = 0.f;
#pragma unroll
        for (int i = 0; i < 4; i++) {
            int c = lane + 32 * i;
            if (c < HID) a += Ms[c] * ow[o * HID + c];
        }
#pragma unroll
        for (int off = 16; off; off >>= 1) a += __shfl_xor_sync(0xffffffffu, a, off);
        if (lane == 0) out[(size_t)n * HID + o] = a + ob[o];
    }
}

// ---------------------------------------------------------------- launch
extern "C" void kernel_launch(void* const* d_in, const int* in_sizes, int n_in,
                              void* d_out, int out_size)
{
    const float* ef       = (const float*)d_in[0];
    const float* et       = (const float*)d_in[1];
    const int*   nid      = (const int*)  d_in[2];
    const int*   idx      = (const int*)  d_in[3];
    const float* lin_w    = (const float*)d_in[4];
    const float* lin_b    = (const float*)d_in[5];
    const float* col_ln_g = (const float*)d_in[6];
    const float* col_ln_b = (const float*)d_in[7];
    const float* col_w1   = (const float*)d_in[8];
    const float* col_b1   = (const float*)d_in[9];
    const float* col_w2   = (const float*)d_in[10];
    const float* col_b2   = (const float*)d_in[11];
    const float* row_ln_g = (const float*)d_in[12];
    const float* row_ln_b = (const float*)d_in[13];
    const float* row_w1   = (const float*)d_in[14];
    const float* row_b1   = (const float*)d_in[15];
    const float* row_w2   = (const float*)d_in[16];
    const float* row_b2   = (const float*)d_in[17];
    const float* norm_g   = (const float*)d_in[18];
    const float* norm_b   = (const float*)d_in[19];
    const float* out_w    = (const float*)d_in[20];
    const float* out_b    = (const float*)d_in[21];
    float* out = (float*)d_out;

    cudaFuncSetAttribute((const void*)k_edge,  cudaFuncAttributeMaxDynamicSharedMemorySize, EDGE_SMEM);
    cudaFuncSetAttribute((const void*)k_mixer, cudaFuncAttributeMaxDynamicSharedMemorySize, MIX_SMEM);

    k_zero<<<(MROWS * HID / 4 + 255) / 256, 256>>>();
    k_prep<<<(448 * 112 + 255) / 256, 256>>>(row_w1, row_w2);
    k_edge<<<E_EDGES / 64, 256, EDGE_SMEM>>>(ef, et, nid, idx, lin_w, lin_b);
    k_colmix<<<(N_N * HID + 255) / 256, 256>>>(col_ln_g, col_ln_b, col_w1, col_b1, col_w2, col_b2);
    k_mixer<<<MROWS / 64, 128, MIX_SMEM>>>(row_ln_g, row_ln_b, row_b1, row_b2);
    k_final<<<N_N, 128>>>(norm_g, norm_b, out_w, out_b, out);
}

// round 8
// speedup vs baseline: 1.8687x; 1.0777x over previous
#include <cuda_runtime.h>
#include <cuda_bf16.h>
#include <math.h>

#define E_EDGES 200000
#define N_N     20000
#define KSLOT   20
#define HID     100
#define TDIM    100
#define EFD     128
#define FIN     228          // EFD + TDIM
#define RH      400
#define MROWS   (N_N*KSLOT)  // 400000
#define LN_EPS  1e-5f

// scratch (device globals; no allocation allowed)
__device__ float g_split[(size_t)MROWS * HID];  // x: scatter target, colmix in-place, residual
__device__ float g_y[(size_t)MROWS * HID];      // mixer output X2
__device__ float g_w1p[448 * 112];              // tf32-rounded, perm16 W1 [448][112]
__device__ float g_w2p[7 * 104 * 64];           // tf32-rounded, perm16 W2 chunks [7][104][64]

__device__ __forceinline__ float gelu_f(float x) {
    return 0.5f * x * (1.0f + erff(x * 0.70710678118654752f));
}

__device__ __forceinline__ unsigned f2tf(float v) {
    unsigned r;
    asm("cvt.rna.tf32.f32 %0, %1;" : "=r"(r) : "f"(v));
    return r;
}
__device__ __forceinline__ float f2tf_f(float v) { return __uint_as_float(f2tf(v)); }

// permute k within each 16-block: thread p's 4 frag elems (k = p, p+4, p+8, p+12) contiguous
__device__ __forceinline__ int kperm16(int k) {
    return (k & ~15) | (((k & 3) << 2) | ((k >> 2) & 3));
}

// ---------------------------------------------------------------- K0: zero split
__global__ void k_zero() {
    size_t i = (size_t)blockIdx.x * blockDim.x + threadIdx.x;
    const size_t n4 = (size_t)MROWS * HID / 4;
    if (i < n4) ((float4*)g_split)[i] = make_float4(0.f, 0.f, 0.f, 0.f);
}

// ---------------------------------------------------------------- K0b: prep weights (tf32 + perm16)
__global__ void k_prep(const float* __restrict__ w1, const float* __restrict__ w2) {
    int i = blockIdx.x * 256 + threadIdx.x;
    if (i < 448 * 112) {
        int ng = i / 112, k = i - ng * 112;
        g_w1p[ng * 112 + kperm16(k)] =
            f2tf_f((ng < RH && k < HID) ? w1[ng * HID + k] : 0.f);
    }
    if (i < 7 * 104 * 64) {
        int ch = i / (104 * 64);
        int r  = i - ch * 104 * 64;
        int n  = r >> 6, k = r & 63;
        g_w2p[(ch * 104 + n) * 64 + kperm16(k)] =
            f2tf_f((n < HID) ? w2[n * RH + ch * 64 + k] : 0.f);
    }
}

// ---------------------------------------------------------------- K1: edge MLP + scatter (fp32)
#define WS_STRIDE 132
#define EDGE_SMEM ((FIN*WS_STRIDE + 64*FIN + TDIM) * 4)

__global__ __launch_bounds__(256) void k_edge(
    const float* __restrict__ ef, const float* __restrict__ et,
    const int* __restrict__ nid, const int* __restrict__ idxp,
    const float* __restrict__ lw, const float* __restrict__ lb)
{
    extern __shared__ float sm1[];
    float* ws = sm1;                       // [228][132]
    float* fs = ws + FIN * WS_STRIDE;      // [64][228]
    float* tw = fs + 64 * FIN;             // [100]
    int tid = threadIdx.x;
    int e0 = blockIdx.x * 64;

    for (int o = tid; o < FIN * WS_STRIDE; o += 256) ws[o] = 0.f;
    if (tid < TDIM) tw[tid] = exp10f(-(9.0f / 99.0f) * (float)tid);
    __syncthreads();

    for (int o = tid; o < HID * FIN; o += 256) {
        int h = o / FIN, j = o - h * FIN;
        ws[j * WS_STRIDE + h] = lw[o];
    }
    for (int o = tid; o < 64 * (EFD / 4); o += 256) {
        int e = o >> 5, j4 = o & 31;
        float4 v = ((const float4*)ef)[(size_t)(e0 + e) * (EFD / 4) + j4];
        float* dst = fs + e * FIN + j4 * 4;
        dst[0] = v.x; dst[1] = v.y; dst[2] = v.z; dst[3] = v.w;
    }
    for (int o = tid; o < 64 * TDIM; o += 256) {
        int e = o / TDIM, t = o - e * TDIM;
        fs[e * FIN + EFD + t] = __cosf(et[e0 + e] * tw[t]);
    }
    __syncthreads();

    int ht = tid & 31;
    int eth = tid >> 5;
    float acc[8][4];
#pragma unroll
    for (int i = 0; i < 8; i++)
#pragma unroll
        for (int j = 0; j < 4; j++) acc[i][j] = 0.f;

    const float* wp = ws + ht * 4;
    const float* fp = fs + eth * 8 * FIN;
    for (int j = 0; j < FIN; j++) {
        float4 w = *(const float4*)(wp + j * WS_STRIDE);
#pragma unroll
        for (int i = 0; i < 8; i++) {
            float f = fp[i * FIN + j];
            acc[i][0] += f * w.x; acc[i][1] += f * w.y;
            acc[i][2] += f * w.z; acc[i][3] += f * w.w;
        }
    }

    int h0 = ht * 4;
    if (h0 < HID) {
        float4 bb = *(const float4*)(lb + h0);
#pragma unroll
        for (int i = 0; i < 8; i++) {
            int e = e0 + eth * 8 + i;
            int pos = nid[e] * KSLOT + idxp[e];
            float4 r = make_float4(acc[i][0] + bb.x, acc[i][1] + bb.y,
                                   acc[i][2] + bb.z, acc[i][3] + bb.w);
            *(float4*)(g_split + (size_t)pos * HID + h0) = r;
        }
    }
}

// ---------------------------------------------------------------- K2: column mixer (coalesced via smem transpose)
__global__ __launch_bounds__(128) void k_colmix(
    const float* __restrict__ cg, const float* __restrict__ cb,
    const float* __restrict__ cw1, const float* __restrict__ cb1,
    const float* __restrict__ cw2, const float* __restrict__ cb2)
{
    __shared__ float t[KSLOT * 104];          // [20][104]
    int tid = threadIdx.x;
    float* base = g_split + (size_t)blockIdx.x * KSLOT * HID;

    // coalesced load: 2000 floats = 500 float4 (25 float4 per row)
    for (int o = tid; o < 500; o += 128) {
        int r = o / 25, c4 = o - r * 25;
        *(float4*)(t + r * 104 + c4 * 4) = *(const float4*)(base + r * HID + c4 * 4);
    }
    __syncthreads();

    if (tid < HID) {
        int c = tid;
        float v[KSLOT]; float s = 0.f;
#pragma unroll
        for (int k = 0; k < KSLOT; k++) { v[k] = t[k * 104 + c]; s += v[k]; }
        float mu = s * (1.0f / KSLOT);
        float s2 = 0.f;
#pragma unroll
        for (int k = 0; k < KSLOT; k++) { float d = v[k] - mu; s2 += d * d; }
        float rs = rsqrtf(s2 * (1.0f / KSLOT) + LN_EPS);

        float vn[KSLOT];
#pragma unroll
        for (int k = 0; k < KSLOT; k++) vn[k] = (v[k] - mu) * rs * cg[k] + cb[k];

        float h1[10];
#pragma unroll
        for (int m = 0; m < 10; m++) {
            float a = cb1[m];
#pragma unroll
            for (int k = 0; k < KSLOT; k++) a += cw1[m * KSLOT + k] * vn[k];
            h1[m] = gelu_f(a);
        }
#pragma unroll
        for (int k = 0; k < KSLOT; k++) {
            float d = cb2[k];
#pragma unroll
            for (int m = 0; m < 10; m++) d += cw2[k * 10 + m] * h1[m];
            t[k * 104 + c] = v[k] + d;
        }
    }
    __syncthreads();

    for (int o = tid; o < 500; o += 128) {
        int r = o / 25, c4 = o - r * 25;
        *(float4*)(base + r * HID + c4 * 4) = *(const float4*)(t + r * 104 + c4 * 4);
    }
}

// ---------------------------------------------------------------- K3: fused row mixer (tf32 mma)
// 64 rows/block, 128 threads = 4 warps = 2 row-groups (32 rows, M=32/warp) x 2 n-halves.
#define SA 112    // Yn/W1s stride (112 mod 32 = 16 -> LDS.128 conflict-free)
#define SH 80     // Hs/W2s stride (64 + 16)
#define NCH 64    // hidden chunk
#define NCHUNK 7  // 448 = 7*64
#define MIX_SMEM ((64*SA + NCH*SA + 64*SH + 104*SH) * 4)   // 111104 B -> 2 blocks/SM

#define MMA_TF32(c,a0,a1,a2,a3,b0,b1) \
    asm volatile("mma.sync.aligned.m16n8k8.row.col.f32.tf32.tf32.f32 " \
        "{%0,%1,%2,%3}, {%4,%5,%6,%7}, {%8,%9}, {%0,%1,%2,%3};" \
        : "+f"(c[0]),"+f"(c[1]),"+f"(c[2]),"+f"(c[3]) \
        : "r"(a0),"r"(a1),"r"(a2),"r"(a3),"r"(b0),"r"(b1))

__global__ __launch_bounds__(128, 2) void k_mixer(
    const float* __restrict__ lng, const float* __restrict__ lnb,
    const float* __restrict__ b1, const float* __restrict__ b2)
{
    extern __shared__ float smx[];
    float* Yn  = smx;                 // [64][SA]
    float* W1s = Yn  + 64 * SA;       // [NCH][SA]
    float* Hs  = W1s + NCH * SA;      // [64][SH]
    float* W2s = Hs  + 64 * SH;       // [104][SH]

    int tid  = threadIdx.x;
    int warp = tid >> 5, lane = tid & 31;
    int q = lane >> 2, p = lane & 3;
    int mgrp = warp & 1;              // row group (32 rows)
    int h    = warp >> 1;             // n-half
    int m0   = mgrp * 32;
    size_t rowBase = (size_t)blockIdx.x * 64;

    // ---- rowLN -> Yn (tf32-rounded, perm16, zero-padded cols 100..111) ----
    for (int rr = 0; rr < 16; rr++) {
        int row = warp * 16 + rr;
        const float* x = g_split + (rowBase + row) * HID;
        float v[4]; float s = 0.f, s2 = 0.f;
#pragma unroll
        for (int i = 0; i < 4; i++) {
            int c = lane + 32 * i;
            v[i] = (c < HID) ? x[c] : 0.f;
            s += v[i]; s2 += v[i] * v[i];
        }
#pragma unroll
        for (int off = 16; off; off >>= 1) {
            s  += __shfl_xor_sync(0xffffffffu, s,  off);
            s2 += __shfl_xor_sync(0xffffffffu, s2, off);
        }
        float mu = s * 0.01f;
        float rs = rsqrtf(s2 * 0.01f - mu * mu + LN_EPS);
#pragma unroll
        for (int i = 0; i < 4; i++) {
            int c = lane + 32 * i;
            if (c < HID)
                Yn[row * SA + kperm16(c)] =
                    f2tf_f((v[i] - mu) * rs * __ldg(lng + c) + __ldg(lnb + c));
        }
        if (lane < SA - HID) Yn[row * SA + kperm16(HID + lane)] = 0.f;
    }

    float acc2[7][4], acc2b[7][4];
#pragma unroll
    for (int i = 0; i < 7; i++)
#pragma unroll
        for (int j = 0; j < 4; j++) { acc2[i][j] = 0.f; acc2b[i][j] = 0.f; }

    for (int ch = 0; ch < NCHUNK; ch++) {
        __syncthreads();   // prior chunk's mma reads done (and LN writes visible) before staging

        // ---- stage W1 chunk [64][112] (pure float4 copy) ----
        {
            const float4* src = (const float4*)(g_w1p + ch * NCH * SA);
            float4* dst = (float4*)W1s;
            for (int o = tid; o < NCH * SA / 4; o += 128) dst[o] = src[o];
        }
        // ---- stage W2 chunk [104][64] -> stride 80 ----
        {
            const float4* src = (const float4*)(g_w2p + ch * 104 * 64);
            for (int o = tid; o < 104 * 16; o += 128) {
                int n = o >> 4, r = o & 15;
                *(float4*)(W2s + n * SH + r * 4) = src[o];
            }
        }
        __syncthreads();

        // ---- GEMM1: H[m0..m0+32)[h*32..h*32+32) ----
        float acc1[2][4][4];
#pragma unroll
        for (int mt = 0; mt < 2; mt++)
#pragma unroll
            for (int nt = 0; nt < 4; nt++)
#pragma unroll
                for (int j = 0; j < 4; j++) acc1[mt][nt][j] = 0.f;

#pragma unroll
        for (int ks = 0; ks < 7; ks++) {          // 7 x k16 over K=112
            float4 a[2][2];
#pragma unroll
            for (int mt = 0; mt < 2; mt++) {
                a[mt][0] = *(const float4*)(Yn + (m0 + mt * 16 + q) * SA + ks * 16 + 4 * p);
                a[mt][1] = *(const float4*)(Yn + (m0 + mt * 16 + q + 8) * SA + ks * 16 + 4 * p);
            }
            float4 bv[4];
#pragma unroll
            for (int nt = 0; nt < 4; nt++)
                bv[nt] = *(const float4*)(W1s + (h * 32 + nt * 8 + q) * SA + ks * 16 + 4 * p);
#pragma unroll
            for (int mt = 0; mt < 2; mt++)
#pragma unroll
                for (int nt = 0; nt < 4; nt++) {
                    MMA_TF32(acc1[mt][nt],
                             __float_as_uint(a[mt][0].x), __float_as_uint(a[mt][1].x),
                             __float_as_uint(a[mt][0].y), __float_as_uint(a[mt][1].y),
                             __float_as_uint(bv[nt].x), __float_as_uint(bv[nt].y));
                    MMA_TF32(acc1[mt][nt],
                             __float_as_uint(a[mt][0].z), __float_as_uint(a[mt][1].z),
                             __float_as_uint(a[mt][0].w), __float_as_uint(a[mt][1].w),
                             __float_as_uint(bv[nt].z), __float_as_uint(bv[nt].w));
                }
        }

        // ---- bias + gelu -> Hs (tf32, perm16 on chunk-local col) ----
#pragma unroll
        for (int nt = 0; nt < 4; nt++) {
            int cl0 = h * 32 + nt * 8 + 2 * p;            // chunk-local col (even)
            int cg0 = ch * NCH + cl0;                     // global hidden col
            float bb0 = (cg0     < RH) ? __ldg(b1 + cg0)     : 0.f;
            float bb1 = (cg0 + 1 < RH) ? __ldg(b1 + cg0 + 1) : 0.f;
            int ps0 = kperm16(cl0), ps1 = kperm16(cl0 + 1);
#pragma unroll
            for (int mt = 0; mt < 2; mt++) {
                float* h0 = Hs + (m0 + mt * 16 + q) * SH;
                float* h1 = Hs + (m0 + mt * 16 + q + 8) * SH;
                h0[ps0] = f2tf_f(gelu_f(acc1[mt][nt][0] + bb0));
                h0[ps1] = f2tf_f(gelu_f(acc1[mt][nt][1] + bb1));
                h1[ps0] = f2tf_f(gelu_f(acc1[mt][nt][2] + bb0));
                h1[ps1] = f2tf_f(gelu_f(acc1[mt][nt][3] + bb1));
            }
        }
        __syncthreads();   // cross-warp: GEMM2 needs both n-halves' H cols

        // ---- GEMM2 accumulate: X2[m0..+32)[tiles of half h] += Hchunk @ W2chunk^T ----
#pragma unroll
        for (int ks = 0; ks < 4; ks++) {          // 4 x k16 over K=64
            float4 a[2][2];
#pragma unroll
            for (int mt = 0; mt < 2; mt++) {
                a[mt][0] = *(const float4*)(Hs + (m0 + mt * 16 + q) * SH + ks * 16 + 4 * p);
                a[mt][1] = *(const float4*)(Hs + (m0 + mt * 16 + q + 8) * SH + ks * 16 + 4 * p);
            }
#pragma unroll
            for (int nt = 0; nt < 7; nt++) {
                if (nt < 7 - h) {                  // h=0: tiles 0..6, h=1: tiles 7..12
                    int tile = h * 7 + nt;
                    float4 bv = *(const float4*)(W2s + (tile * 8 + q) * SH + ks * 16 + 4 * p);
                    MMA_TF32(acc2[nt],
                             __float_as_uint(a[0][0].x), __float_as_uint(a[0][1].x),
                             __float_as_uint(a[0][0].y), __float_as_uint(a[0][1].y),
                             __float_as_uint(bv.x), __float_as_uint(bv.y));
                    MMA_TF32(acc2[nt],
                             __float_as_uint(a[0][0].z), __float_as_uint(a[0][1].z),
                             __float_as_uint(a[0][0].w), __float_as_uint(a[0][1].w),
                             __float_as_uint(bv.z), __float_as_uint(bv.w));
                    MMA_TF32(acc2b[nt],
                             __float_as_uint(a[1][0].x), __float_as_uint(a[1][1].x),
                             __float_as_uint(a[1][0].y), __float_as_uint(a[1][1].y),
                             __float_as_uint(bv.x), __float_as_uint(bv.y));
                    MMA_TF32(acc2b[nt],
                             __float_as_uint(a[1][0].z), __float_as_uint(a[1][1].z),
                             __float_as_uint(a[1][0].w), __float_as_uint(a[1][1].w),
                             __float_as_uint(bv.z), __float_as_uint(bv.w));
                }
            }
        }
    }

    // ---- epilogue: + b2 + residual -> g_y (fp32) ----
#pragma unroll
    for (int nt = 0; nt < 7; nt++) {
        if (nt < 7 - h) {
            int tile = h * 7 + nt;
            int col = tile * 8 + 2 * p;
            if (col < HID) {
                float bb0 = __ldg(b2 + col), bb1 = __ldg(b2 + col + 1);
#pragma unroll
                for (int mt = 0; mt < 2; mt++) {
                    float (*ac)[4] = mt ? acc2b : acc2;
                    size_t r0 = rowBase + m0 + mt * 16 + q, r1 = r0 + 8;
                    float2 x0 = *(const float2*)(g_split + r0 * HID + col);
                    float2 x1 = *(const float2*)(g_split + r1 * HID + col);
                    float2 o0 = make_float2(ac[nt][0] + bb0 + x0.x, ac[nt][1] + bb1 + x0.y);
                    float2 o1 = make_float2(ac[nt][2] + bb0 + x1.x, ac[nt][3] + bb1 + x1.y);
                    *(float2*)(g_y + r0 * HID + col) = o0;
                    *(float2*)(g_y + r1 * HID + col) = o1;
                }
            }
        }
    }
}

// ---------------------------------------------------------------- K4: final LN + mean over K + out proj
__global__ __launch_bounds__(128) void k_final(
    const float* __restrict__ ng, const float* __restrict__ nb,
    const float* __restrict__ ow, const float* __restrict__ ob,
    float* __restrict__ out)
{
    __shared__ float Mp[4][HID];
    __shared__ float Ms[HID];
    int n = blockIdx.x;
    int tid = threadIdx.x, warp = tid >> 5, lane = tid & 31;

    float psum[4] = {0.f, 0.f, 0.f, 0.f};
    for (int rr = 0; rr < 5; rr++) {
        int k = warp * 5 + rr;
        const float* x = g_y + (size_t)(n * KSLOT + k) * HID;
        float v[4]; float s = 0.f, s2 = 0.f;
#pragma unroll
        for (int i = 0; i < 4; i++) {
            int c = lane + 32 * i;
            v[i] = (c < HID) ? x[c] : 0.f;
            s += v[i]; s2 += v[i] * v[i];
        }
#pragma unroll
        for (int off = 16; off; off >>= 1) {
            s  += __shfl_xor_sync(0xffffffffu, s,  off);
            s2 += __shfl_xor_sync(0xffffffffu, s2, off);
        }
        float mu = s * 0.01f;
        float rs = rsqrtf(s2 * 0.01f - mu * mu + LN_EPS);
#pragma unroll
        for (int i = 0; i < 4; i++) {
            int c = lane + 32 * i;
            if (c < HID) psum[i] += (v[i] - mu) * rs * ng[c] + nb[c];
        }
    }
#pragma unroll
    for (int i = 0; i < 4; i++) {
        int c = lane + 32 * i;
        if (c < HID) Mp[warp][c] = psum[i];
    }
    __syncthreads();
    if (tid < HID) Ms[tid] = (Mp[0][tid] + Mp[1][tid] + Mp[2][tid] + Mp[3][tid]) * (1.0f / KSLOT);
    __syncthreads();

    for (int o = warp; o < HID; o += 4) {
        float a = 0.f;
#pragma unroll
        for (int i = 0; i < 4; i++) {
            int c = lane + 32 * i;
            if (c < HID) a += Ms[c] * ow[o * HID + c];
        }
#pragma unroll
        for (int off = 16; off; off >>= 1) a += __shfl_xor_sync(0xffffffffu, a, off);
        if (lane == 0) out[(size_t)n * HID + o] = a + ob[o];
    }
}

// ---------------------------------------------------------------- launch
extern "C" void kernel_launch(void* const* d_in, const int* in_sizes, int n_in,
                              void* d_out, int out_size)
{
    const float* ef       = (const float*)d_in[0];
    const float* et       = (const float*)d_in[1];
    const int*   nid      = (const int*)  d_in[2];
    const int*   idx      = (const int*)  d_in[3];
    const float* lin_w    = (const float*)d_in[4];
    const float* lin_b    = (const float*)d_in[5];
    const float* col_ln_g = (const float*)d_in[6];
    const float* col_ln_b = (const float*)d_in[7];
    const float* col_w1   = (const float*)d_in[8];
    const float* col_b1   = (const float*)d_in[9];
    const float* col_w2   = (const float*)d_in[10];
    const float* col_b2   = (const float*)d_in[11];
    const float* row_ln_g = (const float*)d_in[12];
    const float* row_ln_b = (const float*)d_in[13];
    const float* row_w1   = (const float*)d_in[14];
    const float* row_b1   = (const float*)d_in[15];
    const float* row_w2   = (const float*)d_in[16];
    const float* row_b2   = (const float*)d_in[17];
    const float* norm_g   = (const float*)d_in[18];
    const float* norm_b   = (const float*)d_in[19];
    const float* out_w    = (const float*)d_in[20];
    const float* out_b    = (const float*)d_in[21];
    float* out = (float*)d_out;

    cudaFuncSetAttribute((const void*)k_edge,  cudaFuncAttributeMaxDynamicSharedMemorySize, EDGE_SMEM);
    cudaFuncSetAttribute((const void*)k_mixer, cudaFuncAttributeMaxDynamicSharedMemorySize, MIX_SMEM);

    k_zero<<<(MROWS * HID / 4 + 255) / 256, 256>>>();
    k_prep<<<(448 * 112 + 255) / 256, 256>>>(row_w1, row_w2);
    k_edge<<<E_EDGES / 64, 256, EDGE_SMEM>>>(ef, et, nid, idx, lin_w, lin_b);
    k_colmix<<<N_N, 128>>>(col_ln_g, col_ln_b, col_w1, col_b1, col_w2, col_b2);
    k_mixer<<<MROWS / 64, 128, MIX_SMEM>>>(row_ln_g, row_ln_b, row_b1, row_b2);
    k_final<<<N_N, 128>>>(norm_g, norm_b, out_w, out_b, out);
}

// round 9
// speedup vs baseline: 2.3092x; 1.2357x over previous
#include <cuda_runtime.h>
#include <cuda_bf16.h>
#include <math.h>

#define E_EDGES 200000
#define N_N     20000
#define KSLOT   20
#define HID     100
#define TDIM    100
#define EFD     128
#define FIN     228          // EFD + TDIM
#define RH      400
#define MROWS   (N_N*KSLOT)  // 400000
#define LN_EPS  1e-5f

// scratch (device globals; no allocation allowed)
__device__ float g_split[(size_t)MROWS * HID];  // x: scatter target, colmix in-place, residual
__device__ float g_y[(size_t)MROWS * HID];      // mixer output X2
__device__ float g_w1p[448 * 112];              // tf32+perm16 W1 [448][112]
__device__ float g_w2p[7 * 104 * 64];           // tf32+perm16 W2 chunks [7][104][64]
__device__ float g_wep[112 * 240];              // tf32+perm16 edge W [112][240]
__device__ float g_tw[128];                     // time-encode freqs (padded)

__device__ __forceinline__ float gelu_f(float x) {
    return 0.5f * x * (1.0f + erff(x * 0.70710678118654752f));
}

__device__ __forceinline__ unsigned f2tf(float v) {
    unsigned r;
    asm("cvt.rna.tf32.f32 %0, %1;" : "=r"(r) : "f"(v));
    return r;
}
__device__ __forceinline__ float f2tf_f(float v) { return __uint_as_float(f2tf(v)); }

// permute k within each 16-block: thread p's 4 frag elems (k = p, p+4, p+8, p+12) contiguous
__device__ __forceinline__ int kperm16(int k) {
    return (k & ~15) | (((k & 3) << 2) | ((k >> 2) & 3));
}

#define MMA_TF32(c,a0,a1,a2,a3,b0,b1) \
    asm volatile("mma.sync.aligned.m16n8k8.row.col.f32.tf32.tf32.f32 " \
        "{%0,%1,%2,%3}, {%4,%5,%6,%7}, {%8,%9}, {%0,%1,%2,%3};" \
        : "+f"(c[0]),"+f"(c[1]),"+f"(c[2]),"+f"(c[3]) \
        : "r"(a0),"r"(a1),"r"(a2),"r"(a3),"r"(b0),"r"(b1))

// ---------------------------------------------------------------- K0: init (zero split + all weight prep)
__global__ void k_init(const float* __restrict__ w1, const float* __restrict__ w2,
                       const float* __restrict__ lw) {
    int i = blockIdx.x * 256 + threadIdx.x;
    const int n4 = MROWS * HID / 4;            // 10,000,000
    if (i < n4) ((float4*)g_split)[i] = make_float4(0.f, 0.f, 0.f, 0.f);
    if (i < 448 * 112) {
        int ng = i / 112, k = i - ng * 112;
        g_w1p[ng * 112 + kperm16(k)] =
            f2tf_f((ng < RH && k < HID) ? w1[ng * HID + k] : 0.f);
    }
    if (i < 7 * 104 * 64) {
        int ch = i / (104 * 64);
        int r  = i - ch * 104 * 64;
        int n  = r >> 6, k = r & 63;
        g_w2p[(ch * 104 + n) * 64 + kperm16(k)] =
            f2tf_f((n < HID) ? w2[n * RH + ch * 64 + k] : 0.f);
    }
    if (i < 112 * 240) {
        int n = i / 240, k = i - n * 240;
        g_wep[n * 240 + kperm16(k)] =
            f2tf_f((n < HID && k < FIN) ? lw[n * FIN + k] : 0.f);
    }
    if (i < 128) g_tw[i] = (i < TDIM) ? exp10f(-(9.0f / 99.0f) * (float)i) : 0.f;
}

// ---------------------------------------------------------------- K1: edge MLP (tf32 mma) + scatter
// 64 edges/block, 256 threads = 8 warps = 4 m-groups (16 edges) x 2 n-halves.
#define ESA 240          // fs stride (240 mod 32 = 16 -> LDS.128 conflict-free)
#define EDGE_SMEM (64 * ESA * 4)   // 61440 B -> 2 blocks/SM

__global__ __launch_bounds__(256, 2) void k_edge(
    const float* __restrict__ ef, const float* __restrict__ et,
    const int* __restrict__ nid, const int* __restrict__ idxp,
    const float* __restrict__ lb)
{
    extern __shared__ float fs[];    // [64][240] tf32, perm16
    int tid = threadIdx.x;
    int e0 = blockIdx.x * 64;

    // ---- build features: ef part (cols 0..127) ----
    for (int o = tid; o < 64 * 32; o += 256) {
        int e = o >> 5, j4 = o & 31;
        float4 v = ((const float4*)ef)[(size_t)(e0 + e) * 32 + j4];
        float* dst = fs + e * ESA;
        int k0 = j4 * 4;
        dst[kperm16(k0)]     = f2tf_f(v.x);
        dst[kperm16(k0 + 1)] = f2tf_f(v.y);
        dst[kperm16(k0 + 2)] = f2tf_f(v.z);
        dst[kperm16(k0 + 3)] = f2tf_f(v.w);
    }
    // ---- time encoding (cols 128..227) + zero pad (228..239) ----
    for (int o = tid; o < 64 * 112; o += 256) {
        int e = o / 112, tt = o - e * 112;
        float val = 0.f;
        if (tt < TDIM) val = __cosf(et[e0 + e] * __ldg(g_tw + tt));
        fs[e * ESA + kperm16(128 + tt)] = f2tf_f(val);
    }
    __syncthreads();

    int warp = tid >> 5, lane = tid & 31;
    int q = lane >> 2, p = lane & 3;
    int mgrp = warp & 3, h = warp >> 2;
    int m0 = mgrp * 16;

    float acc[7][4];
#pragma unroll
    for (int i = 0; i < 7; i++)
#pragma unroll
        for (int j = 0; j < 4; j++) acc[i][j] = 0.f;

#pragma unroll
    for (int ks = 0; ks < 15; ks++) {          // 15 x k16 over K=240
        float4 a0 = *(const float4*)(fs + (m0 + q) * ESA + ks * 16 + 4 * p);
        float4 a1 = *(const float4*)(fs + (m0 + q + 8) * ESA + ks * 16 + 4 * p);
#pragma unroll
        for (int nt = 0; nt < 7; nt++) {
            float4 bv = *(const float4*)(g_wep + ((h * 7 + nt) * 8 + q) * ESA + ks * 16 + 4 * p);
            MMA_TF32(acc[nt],
                     __float_as_uint(a0.x), __float_as_uint(a1.x),
                     __float_as_uint(a0.y), __float_as_uint(a1.y),
                     __float_as_uint(bv.x), __float_as_uint(bv.y));
            MMA_TF32(acc[nt],
                     __float_as_uint(a0.z), __float_as_uint(a1.z),
                     __float_as_uint(a0.w), __float_as_uint(a1.w),
                     __float_as_uint(bv.z), __float_as_uint(bv.w));
        }
    }

    // ---- epilogue: bias + scatter (unique positions -> plain stores) ----
    int e1 = e0 + m0 + q, e2 = e1 + 8;
    int pos1 = nid[e1] * KSLOT + idxp[e1];
    int pos2 = nid[e2] * KSLOT + idxp[e2];
#pragma unroll
    for (int nt = 0; nt < 7; nt++) {
        int col = (h * 7 + nt) * 8 + 2 * p;
        if (col < HID) {
            float b0 = __ldg(lb + col), b1 = __ldg(lb + col + 1);
            *(float2*)(g_split + (size_t)pos1 * HID + col) =
                make_float2(acc[nt][0] + b0, acc[nt][1] + b1);
            *(float2*)(g_split + (size_t)pos2 * HID + col) =
                make_float2(acc[nt][2] + b0, acc[nt][3] + b1);
        }
    }
}

// ---------------------------------------------------------------- K2: column mixer v3 (8 nodes/block, all threads active)
#define CMX_SMEM ((8 * 2080 + 512) * 4)

__global__ __launch_bounds__(256) void k_colmix(
    const float* __restrict__ cg, const float* __restrict__ cb,
    const float* __restrict__ cw1, const float* __restrict__ cb1,
    const float* __restrict__ cw2, const float* __restrict__ cb2)
{
    extern __shared__ float sm2[];
    float* t   = sm2;                  // 8 nodes x [20][104]
    float* w1s = sm2 + 8 * 2080;       // [200]
    float* w2s = w1s + 200;            // [200]
    float* gs  = w2s + 200;            // [20]
    float* bs  = gs + 20;              // [20]
    float* b1s = bs + 20;              // [10]
    float* b2s = b1s + 10;             // [20]
    int tid = threadIdx.x;
    float* base = g_split + (size_t)blockIdx.x * 8 * KSLOT * HID;

    for (int o = tid; o < 200; o += 256) { w1s[o] = cw1[o]; w2s[o] = cw2[o]; }
    if (tid < 20) { gs[tid] = cg[tid]; bs[tid] = cb[tid]; b2s[tid] = cb2[tid]; }
    if (tid >= 32 && tid < 42) b1s[tid - 32] = cb1[tid - 32];

    // coalesced load: 8 nodes x 2000 floats = 4000 float4
    for (int o = tid; o < 4000; o += 256) {
        int node = o / 500, r = o % 500;
        int k = r / 25, c4 = r - k * 25;
        *(float4*)(t + node * 2080 + k * 104 + c4 * 4) =
            *(const float4*)(base + (node * KSLOT + k) * HID + c4 * 4);
    }
    __syncthreads();

    int node = tid >> 5, lane = tid & 31;
    float* tb = t + node * 2080;
#pragma unroll
    for (int i = 0; i < 4; i++) {
        int c = lane + 32 * i;
        if (c < HID) {
            float v[KSLOT]; float s = 0.f;
#pragma unroll
            for (int k = 0; k < KSLOT; k++) { v[k] = tb[k * 104 + c]; s += v[k]; }
            float mu = s * (1.0f / KSLOT);
            float s2 = 0.f;
#pragma unroll
            for (int k = 0; k < KSLOT; k++) { float d = v[k] - mu; s2 += d * d; }
            float rs = rsqrtf(s2 * (1.0f / KSLOT) + LN_EPS);

            float vn[KSLOT];
#pragma unroll
            for (int k = 0; k < KSLOT; k++) vn[k] = (v[k] - mu) * rs * gs[k] + bs[k];

            float h1[10];
#pragma unroll
            for (int m = 0; m < 10; m++) {
                float a = b1s[m];
#pragma unroll
                for (int k = 0; k < KSLOT; k++) a += w1s[m * KSLOT + k] * vn[k];
                h1[m] = gelu_f(a);
            }
#pragma unroll
            for (int k = 0; k < KSLOT; k++) {
                float d = b2s[k];
#pragma unroll
                for (int m = 0; m < 10; m++) d += w2s[k * 10 + m] * h1[m];
                tb[k * 104 + c] = v[k] + d;
            }
        }
    }
    __syncthreads();

    for (int o = tid; o < 4000; o += 256) {
        int node = o / 500, r = o % 500;
        int k = r / 25, c4 = r - k * 25;
        *(float4*)(base + (node * KSLOT + k) * HID + c4 * 4) =
            *(const float4*)(t + node * 2080 + k * 104 + c4 * 4);
    }
}

// ---------------------------------------------------------------- K3: fused row mixer (tf32 mma) — unchanged from R8
#define SA 112
#define SH 80
#define NCH 64
#define NCHUNK 7
#define MIX_SMEM ((64*SA + NCH*SA + 64*SH + 104*SH) * 4)   // 111104 B -> 2 blocks/SM

__global__ __launch_bounds__(128, 2) void k_mixer(
    const float* __restrict__ lng, const float* __restrict__ lnb,
    const float* __restrict__ b1, const float* __restrict__ b2)
{
    extern __shared__ float smx[];
    float* Yn  = smx;                 // [64][SA]
    float* W1s = Yn  + 64 * SA;       // [NCH][SA]
    float* Hs  = W1s + NCH * SA;      // [64][SH]
    float* W2s = Hs  + 64 * SH;       // [104][SH]

    int tid  = threadIdx.x;
    int warp = tid >> 5, lane = tid & 31;
    int q = lane >> 2, p = lane & 3;
    int mgrp = warp & 1;
    int h    = warp >> 1;
    int m0   = mgrp * 32;
    size_t rowBase = (size_t)blockIdx.x * 64;

    for (int rr = 0; rr < 16; rr++) {
        int row = warp * 16 + rr;
        const float* x = g_split + (rowBase + row) * HID;
        float v[4]; float s = 0.f, s2 = 0.f;
#pragma unroll
        for (int i = 0; i < 4; i++) {
            int c = lane + 32 * i;
            v[i] = (c < HID) ? x[c] : 0.f;
            s += v[i]; s2 += v[i] * v[i];
        }
#pragma unroll
        for (int off = 16; off; off >>= 1) {
            s  += __shfl_xor_sync(0xffffffffu, s,  off);
            s2 += __shfl_xor_sync(0xffffffffu, s2, off);
        }
        float mu = s * 0.01f;
        float rs = rsqrtf(s2 * 0.01f - mu * mu + LN_EPS);
#pragma unroll
        for (int i = 0; i < 4; i++) {
            int c = lane + 32 * i;
            if (c < HID)
                Yn[row * SA + kperm16(c)] =
                    f2tf_f((v[i] - mu) * rs * __ldg(lng + c) + __ldg(lnb + c));
        }
        if (lane < SA - HID) Yn[row * SA + kperm16(HID + lane)] = 0.f;
    }

    float acc2[7][4], acc2b[7][4];
#pragma unroll
    for (int i = 0; i < 7; i++)
#pragma unroll
        for (int j = 0; j < 4; j++) { acc2[i][j] = 0.f; acc2b[i][j] = 0.f; }

    for (int ch = 0; ch < NCHUNK; ch++) {
        __syncthreads();

        {
            const float4* src = (const float4*)(g_w1p + ch * NCH * SA);
            float4* dst = (float4*)W1s;
            for (int o = tid; o < NCH * SA / 4; o += 128) dst[o] = src[o];
        }
        {
            const float4* src = (const float4*)(g_w2p + ch * 104 * 64);
            for (int o = tid; o < 104 * 16; o += 128) {
                int n = o >> 4, r = o & 15;
                *(float4*)(W2s + n * SH + r * 4) = src[o];
            }
        }
        __syncthreads();

        float acc1[2][4][4];
#pragma unroll
        for (int mt = 0; mt < 2; mt++)
#pragma unroll
            for (int nt = 0; nt < 4; nt++)
#pragma unroll
                for (int j = 0; j < 4; j++) acc1[mt][nt][j] = 0.f;

#pragma unroll
        for (int ks = 0; ks < 7; ks++) {
            float4 a[2][2];
#pragma unroll
            for (int mt = 0; mt < 2; mt++) {
                a[mt][0] = *(const float4*)(Yn + (m0 + mt * 16 + q) * SA + ks * 16 + 4 * p);
                a[mt][1] = *(const float4*)(Yn + (m0 + mt * 16 + q + 8) * SA + ks * 16 + 4 * p);
            }
            float4 bv[4];
#pragma unroll
            for (int nt = 0; nt < 4; nt++)
                bv[nt] = *(const float4*)(W1s + (h * 32 + nt * 8 + q) * SA + ks * 16 + 4 * p);
#pragma unroll
            for (int mt = 0; mt < 2; mt++)
#pragma unroll
                for (int nt = 0; nt < 4; nt++) {
                    MMA_TF32(acc1[mt][nt],
                             __float_as_uint(a[mt][0].x), __float_as_uint(a[mt][1].x),
                             __float_as_uint(a[mt][0].y), __float_as_uint(a[mt][1].y),
                             __float_as_uint(bv[nt].x), __float_as_uint(bv[nt].y));
                    MMA_TF32(acc1[mt][nt],
                             __float_as_uint(a[mt][0].z), __float_as_uint(a[mt][1].z),
                             __float_as_uint(a[mt][0].w), __float_as_uint(a[mt][1].w),
                             __float_as_uint(bv[nt].z), __float_as_uint(bv[nt].w));
                }
        }

#pragma unroll
        for (int nt = 0; nt < 4; nt++) {
            int cl0 = h * 32 + nt * 8 + 2 * p;
            int cg0 = ch * NCH + cl0;
            float bb0 = (cg0     < RH) ? __ldg(b1 + cg0)     : 0.f;
            float bb1 = (cg0 + 1 < RH) ? __ldg(b1 + cg0 + 1) : 0.f;
            int ps0 = kperm16(cl0), ps1 = kperm16(cl0 + 1);
#pragma unroll
            for (int mt = 0; mt < 2; mt++) {
                float* h0 = Hs + (m0 + mt * 16 + q) * SH;
                float* h1 = Hs + (m0 + mt * 16 + q + 8) * SH;
                h0[ps0] = f2tf_f(gelu_f(acc1[mt][nt][0] + bb0));
                h0[ps1] = f2tf_f(gelu_f(acc1[mt][nt][1] + bb1));
                h1[ps0] = f2tf_f(gelu_f(acc1[mt][nt][2] + bb0));
                h1[ps1] = f2tf_f(gelu_f(acc1[mt][nt][3] + bb1));
            }
        }
        __syncthreads();

#pragma unroll
        for (int ks = 0; ks < 4; ks++) {
            float4 a[2][2];
#pragma unroll
            for (int mt = 0; mt < 2; mt++) {
                a[mt][0] = *(const float4*)(Hs + (m0 + mt * 16 + q) * SH + ks * 16 + 4 * p);
                a[mt][1] = *(const float4*)(Hs + (m0 + mt * 16 + q + 8) * SH + ks * 16 + 4 * p);
            }
#pragma unroll
            for (int nt = 0; nt < 7; nt++) {
                if (nt < 7 - h) {
                    int tile = h * 7 + nt;
                    float4 bv = *(const float4*)(W2s + (tile * 8 + q) * SH + ks * 16 + 4 * p);
                    MMA_TF32(acc2[nt],
                             __float_as_uint(a[0][0].x), __float_as_uint(a[0][1].x),
                             __float_as_uint(a[0][0].y), __float_as_uint(a[0][1].y),
                             __float_as_uint(bv.x), __float_as_uint(bv.y));
                    MMA_TF32(acc2[nt],
                             __float_as_uint(a[0][0].z), __float_as_uint(a[0][1].z),
                             __float_as_uint(a[0][0].w), __float_as_uint(a[0][1].w),
                             __float_as_uint(bv.z), __float_as_uint(bv.w));
                    MMA_TF32(acc2b[nt],
                             __float_as_uint(a[1][0].x), __float_as_uint(a[1][1].x),
                             __float_as_uint(a[1][0].y), __float_as_uint(a[1][1].y),
                             __float_as_uint(bv.x), __float_as_uint(bv.y));
                    MMA_TF32(acc2b[nt],
                             __float_as_uint(a[1][0].z), __float_as_uint(a[1][1].z),
                             __float_as_uint(a[1][0].w), __float_as_uint(a[1][1].w),
                             __float_as_uint(bv.z), __float_as_uint(bv.w));
                }
            }
        }
    }

#pragma unroll
    for (int nt = 0; nt < 7; nt++) {
        if (nt < 7 - h) {
            int tile = h * 7 + nt;
            int col = tile * 8 + 2 * p;
            if (col < HID) {
                float bb0 = __ldg(b2 + col), bb1 = __ldg(b2 + col + 1);
#pragma unroll
                for (int mt = 0; mt < 2; mt++) {
                    float (*ac)[4] = mt ? acc2b : acc2;
                    size_t r0 = rowBase + m0 + mt * 16 + q, r1 = r0 + 8;
                    float2 x0 = *(const float2*)(g_split + r0 * HID + col);
                    float2 x1 = *(const float2*)(g_split + r1 * HID + col);
                    float2 o0 = make_float2(ac[nt][0] + bb0 + x0.x, ac[nt][1] + bb1 + x0.y);
                    float2 o1 = make_float2(ac[nt][2] + bb0 + x1.x, ac[nt][3] + bb1 + x1.y);
                    *(float2*)(g_y + r0 * HID + col) = o0;
                    *(float2*)(g_y + r1 * HID + col) = o1;
                }
            }
        }
    }
}

// ---------------------------------------------------------------- K4: final LN + mean over K + out proj
__global__ __launch_bounds__(128) void k_final(
    const float* __restrict__ ng, const float* __restrict__ nb,
    const float* __restrict__ ow, const float* __restrict__ ob,
    float* __restrict__ out)
{
    __shared__ float Mp[4][HID];
    __shared__ float Ms[HID];
    int n = blockIdx.x;
    int tid = threadIdx.x, warp = tid >> 5, lane = tid & 31;

    float psum[4] = {0.f, 0.f, 0.f, 0.f};
    for (int rr = 0; rr < 5; rr++) {
        int k = warp * 5 + rr;
        const float* x = g_y + (size_t)(n * KSLOT + k) * HID;
        float v[4]; float s = 0.f, s2 = 0.f;
#pragma unroll
        for (int i = 0; i < 4; i++) {
            int c = lane + 32 * i;
            v[i] = (c < HID) ? x[c] : 0.f;
            s += v[i]; s2 += v[i] * v[i];
        }
#pragma unroll
        for (int off = 16; off; off >>= 1) {
            s  += __shfl_xor_sync(0xffffffffu, s,  off);
            s2 += __shfl_xor_sync(0xffffffffu, s2, off);
        }
        float mu = s * 0.01f;
        float rs = rsqrtf(s2 * 0.01f - mu * mu + LN_EPS);
#pragma unroll
        for (int i = 0; i < 4; i++) {
            int c = lane + 32 * i;
            if (c < HID) psum[i] += (v[i] - mu) * rs * ng[c] + nb[c];
        }
    }
#pragma unroll
    for (int i = 0; i < 4; i++) {
        int c = lane + 32 * i;
        if (c < HID) Mp[warp][c] = psum[i];
    }
    __syncthreads();
    if (tid < HID) Ms[tid] = (Mp[0][tid] + Mp[1][tid] + Mp[2][tid] + Mp[3][tid]) * (1.0f / KSLOT);
    __syncthreads();

    for (int o = warp; o < HID; o += 4) {
        float a = 0.f;
#pragma unroll
        for (int i = 0; i < 4; i++) {
            int c = lane + 32 * i;
            if (c < HID) a += Ms[c] * ow[o * HID + c];
        }
#pragma unroll
        for (int off = 16; off; off >>= 1) a += __shfl_xor_sync(0xffffffffu, a, off);
        if (lane == 0) out[(size_t)n * HID + o] = a + ob[o];
    }
}

// ---------------------------------------------------------------- launch
extern "C" void kernel_launch(void* const* d_in, const int* in_sizes, int n_in,
                              void* d_out, int out_size)
{
    const float* ef       = (const float*)d_in[0];
    const float* et       = (const float*)d_in[1];
    const int*   nid      = (const int*)  d_in[2];
    const int*   idx      = (const int*)  d_in[3];
    const float* lin_w    = (const float*)d_in[4];
    const float* lin_b    = (const float*)d_in[5];
    const float* col_ln_g = (const float*)d_in[6];
    const float* col_ln_b = (const float*)d_in[7];
    const float* col_w1   = (const float*)d_in[8];
    const float* col_b1   = (const float*)d_in[9];
    const float* col_w2   = (const float*)d_in[10];
    const float* col_b2   = (const float*)d_in[11];
    const float* row_ln_g = (const float*)d_in[12];
    const float* row_ln_b = (const float*)d_in[13];
    const float* row_w1   = (const float*)d_in[14];
    const float* row_b1   = (const float*)d_in[15];
    const float* row_w2   = (const float*)d_in[16];
    const float* row_b2   = (const float*)d_in[17];
    const float* norm_g   = (const float*)d_in[18];
    const float* norm_b   = (const float*)d_in[19];
    const float* out_w    = (const float*)d_in[20];
    const float* out_b    = (const float*)d_in[21];
    float* out = (float*)d_out;

    cudaFuncSetAttribute((const void*)k_edge,   cudaFuncAttributeMaxDynamicSharedMemorySize, EDGE_SMEM);
    cudaFuncSetAttribute((const void*)k_colmix, cudaFuncAttributeMaxDynamicSharedMemorySize, CMX_SMEM);
    cudaFuncSetAttribute((const void*)k_mixer,  cudaFuncAttributeMaxDynamicSharedMemorySize, MIX_SMEM);

    k_init<<<(MROWS * HID / 4 + 255) / 256, 256>>>(row_w1, row_w2, lin_w);
    k_edge<<<E_EDGES / 64, 256, EDGE_SMEM>>>(ef, et, nid, idx, lin_b);
    k_colmix<<<N_N / 8, 256, CMX_SMEM>>>(col_ln_g, col_ln_b, col_w1, col_b1, col_w2, col_b2);
    k_mixer<<<MROWS / 64, 128, MIX_SMEM>>>(row_ln_g, row_ln_b, row_b1, row_b2);
    k_final<<<N_N, 128>>>(norm_g, norm_b, out_w, out_b, out);
}

// round 10
// speedup vs baseline: 2.8461x; 1.2325x over previous
#include <cuda_runtime.h>
#include <cuda_bf16.h>
#include <math.h>

#define E_EDGES 200000
#define N_N     20000
#define KSLOT   20
#define HID     100
#define TDIM    100
#define EFD     128
#define FIN     228          // EFD + TDIM
#define RH      400
#define MROWS   (N_N*KSLOT)  // 400000
#define LN_EPS  1e-5f

// scratch (device globals; no allocation allowed)
__device__ float g_split[(size_t)MROWS * HID];  // x: scatter target, colmix in-place, residual
__device__ float g_y[(size_t)MROWS * HID];      // mixer output X2
__device__ float g_w1p[448 * 112];              // tf32+perm16 W1 [448][112]
__device__ float g_w2p[7 * 104 * 64];           // tf32+perm16 W2 chunks [7][104][64]
__device__ float g_wep[112 * 240];              // tf32+perm16 edge W [112][240]
__device__ float g_tw[128];                     // time-encode freqs (padded)

__device__ __forceinline__ float gelu_f(float x) {
    return 0.5f * x * (1.0f + erff(x * 0.70710678118654752f));
}

__device__ __forceinline__ unsigned f2tf(float v) {
    unsigned r;
    asm("cvt.rna.tf32.f32 %0, %1;" : "=r"(r) : "f"(v));
    return r;
}
__device__ __forceinline__ float f2tf_f(float v) { return __uint_as_float(f2tf(v)); }

// permute k within each 16-block: thread p's 4 frag elems (k = p, p+4, p+8, p+12) contiguous
__device__ __forceinline__ int kperm16(int k) {
    return (k & ~15) | (((k & 3) << 2) | ((k >> 2) & 3));
}

#define MMA_TF32(c,a0,a1,a2,a3,b0,b1) \
    asm volatile("mma.sync.aligned.m16n8k8.row.col.f32.tf32.tf32.f32 " \
        "{%0,%1,%2,%3}, {%4,%5,%6,%7}, {%8,%9}, {%0,%1,%2,%3};" \
        : "+f"(c[0]),"+f"(c[1]),"+f"(c[2]),"+f"(c[3]) \
        : "r"(a0),"r"(a1),"r"(a2),"r"(a3),"r"(b0),"r"(b1))

// ---------------------------------------------------------------- K0: init (zero split + all weight prep)
__global__ void k_init(const float* __restrict__ w1, const float* __restrict__ w2,
                       const float* __restrict__ lw) {
    int i = blockIdx.x * 256 + threadIdx.x;
    const int n4 = MROWS * HID / 4;            // 10,000,000
    if (i < n4) ((float4*)g_split)[i] = make_float4(0.f, 0.f, 0.f, 0.f);
    if (i < 448 * 112) {
        int ng = i / 112, k = i - ng * 112;
        g_w1p[ng * 112 + kperm16(k)] =
            f2tf_f((ng < RH && k < HID) ? w1[ng * HID + k] : 0.f);
    }
    if (i < 7 * 104 * 64) {
        int ch = i / (104 * 64);
        int r  = i - ch * 104 * 64;
        int n  = r >> 6, k = r & 63;
        g_w2p[(ch * 104 + n) * 64 + kperm16(k)] =
            f2tf_f((n < HID) ? w2[n * RH + ch * 64 + k] : 0.f);
    }
    if (i < 112 * 240) {
        int n = i / 240, k = i - n * 240;
        g_wep[n * 240 + kperm16(k)] =
            f2tf_f((n < HID && k < FIN) ? lw[n * FIN + k] : 0.f);
    }
    if (i < 128) g_tw[i] = (i < TDIM) ? exp10f(-(9.0f / 99.0f) * (float)i) : 0.f;
}

// ---------------------------------------------------------------- K1: edge MLP (tf32 mma) + scatter
// 64 edges/block, 256 threads = 8 warps = 4 m-groups (16 edges) x 2 n-halves.
#define ESA 240          // fs stride (240 mod 32 = 16 -> LDS.128 conflict-free)
#define EDGE_SMEM (64 * ESA * 4)   // 61440 B -> 2 blocks/SM

__global__ __launch_bounds__(256, 2) void k_edge(
    const float* __restrict__ ef, const float* __restrict__ et,
    const int* __restrict__ nid, const int* __restrict__ idxp,
    const float* __restrict__ lb)
{
    extern __shared__ float fs[];    // [64][240] tf32, perm16
    int tid = threadIdx.x;
    int e0 = blockIdx.x * 64;

    // ---- build features: ef part (cols 0..127) ----
    for (int o = tid; o < 64 * 32; o += 256) {
        int e = o >> 5, j4 = o & 31;
        float4 v = ((const float4*)ef)[(size_t)(e0 + e) * 32 + j4];
        float* dst = fs + e * ESA;
        int k0 = j4 * 4;
        dst[kperm16(k0)]     = f2tf_f(v.x);
        dst[kperm16(k0 + 1)] = f2tf_f(v.y);
        dst[kperm16(k0 + 2)] = f2tf_f(v.z);
        dst[kperm16(k0 + 3)] = f2tf_f(v.w);
    }
    // ---- time encoding (cols 128..227) + zero pad (228..239) ----
    for (int o = tid; o < 64 * 112; o += 256) {
        int e = o / 112, tt = o - e * 112;
        float val = 0.f;
        if (tt < TDIM) val = __cosf(et[e0 + e] * __ldg(g_tw + tt));
        fs[e * ESA + kperm16(128 + tt)] = f2tf_f(val);
    }
    __syncthreads();

    int warp = tid >> 5, lane = tid & 31;
    int q = lane >> 2, p = lane & 3;
    int mgrp = warp & 3, h = warp >> 2;
    int m0 = mgrp * 16;

    float acc[7][4];
#pragma unroll
    for (int i = 0; i < 7; i++)
#pragma unroll
        for (int j = 0; j < 4; j++) acc[i][j] = 0.f;

#pragma unroll
    for (int ks = 0; ks < 15; ks++) {          // 15 x k16 over K=240
        float4 a0 = *(const float4*)(fs + (m0 + q) * ESA + ks * 16 + 4 * p);
        float4 a1 = *(const float4*)(fs + (m0 + q + 8) * ESA + ks * 16 + 4 * p);
#pragma unroll
        for (int nt = 0; nt < 7; nt++) {
            float4 bv = *(const float4*)(g_wep + ((h * 7 + nt) * 8 + q) * ESA + ks * 16 + 4 * p);
            MMA_TF32(acc[nt],
                     __float_as_uint(a0.x), __float_as_uint(a1.x),
                     __float_as_uint(a0.y), __float_as_uint(a1.y),
                     __float_as_uint(bv.x), __float_as_uint(bv.y));
            MMA_TF32(acc[nt],
                     __float_as_uint(a0.z), __float_as_uint(a1.z),
                     __float_as_uint(a0.w), __float_as_uint(a1.w),
                     __float_as_uint(bv.z), __float_as_uint(bv.w));
        }
    }

    // ---- epilogue: bias + scatter (unique positions -> plain stores) ----
    int e1 = e0 + m0 + q, e2 = e1 + 8;
    int pos1 = nid[e1] * KSLOT + idxp[e1];
    int pos2 = nid[e2] * KSLOT + idxp[e2];
#pragma unroll
    for (int nt = 0; nt < 7; nt++) {
        int col = (h * 7 + nt) * 8 + 2 * p;
        if (col < HID) {
            float b0 = __ldg(lb + col), b1 = __ldg(lb + col + 1);
            *(float2*)(g_split + (size_t)pos1 * HID + col) =
                make_float2(acc[nt][0] + b0, acc[nt][1] + b1);
            *(float2*)(g_split + (size_t)pos2 * HID + col) =
                make_float2(acc[nt][2] + b0, acc[nt][3] + b1);
        }
    }
}

// ---------------------------------------------------------------- K2: column mixer v3 (8 nodes/block)
#define CMX_SMEM ((8 * 2080 + 512) * 4)

__global__ __launch_bounds__(256) void k_colmix(
    const float* __restrict__ cg, const float* __restrict__ cb,
    const float* __restrict__ cw1, const float* __restrict__ cb1,
    const float* __restrict__ cw2, const float* __restrict__ cb2)
{
    extern __shared__ float sm2[];
    float* t   = sm2;                  // 8 nodes x [20][104]
    float* w1s = sm2 + 8 * 2080;       // [200]
    float* w2s = w1s + 200;            // [200]
    float* gs  = w2s + 200;            // [20]
    float* bs  = gs + 20;              // [20]
    float* b1s = bs + 20;              // [10]
    float* b2s = b1s + 10;             // [20]
    int tid = threadIdx.x;
    float* base = g_split + (size_t)blockIdx.x * 8 * KSLOT * HID;

    for (int o = tid; o < 200; o += 256) { w1s[o] = cw1[o]; w2s[o] = cw2[o]; }
    if (tid < 20) { gs[tid] = cg[tid]; bs[tid] = cb[tid]; b2s[tid] = cb2[tid]; }
    if (tid >= 32 && tid < 42) b1s[tid - 32] = cb1[tid - 32];

    for (int o = tid; o < 4000; o += 256) {
        int node = o / 500, r = o % 500;
        int k = r / 25, c4 = r - k * 25;
        *(float4*)(t + node * 2080 + k * 104 + c4 * 4) =
            *(const float4*)(base + (node * KSLOT + k) * HID + c4 * 4);
    }
    __syncthreads();

    int node = tid >> 5, lane = tid & 31;
    float* tb = t + node * 2080;
#pragma unroll
    for (int i = 0; i < 4; i++) {
        int c = lane + 32 * i;
        if (c < HID) {
            float v[KSLOT]; float s = 0.f;
#pragma unroll
            for (int k = 0; k < KSLOT; k++) { v[k] = tb[k * 104 + c]; s += v[k]; }
            float mu = s * (1.0f / KSLOT);
            float s2 = 0.f;
#pragma unroll
            for (int k = 0; k < KSLOT; k++) { float d = v[k] - mu; s2 += d * d; }
            float rs = rsqrtf(s2 * (1.0f / KSLOT) + LN_EPS);

            float vn[KSLOT];
#pragma unroll
            for (int k = 0; k < KSLOT; k++) vn[k] = (v[k] - mu) * rs * gs[k] + bs[k];

            float h1[10];
#pragma unroll
            for (int m = 0; m < 10; m++) {
                float a = b1s[m];
#pragma unroll
                for (int k = 0; k < KSLOT; k++) a += w1s[m * KSLOT + k] * vn[k];
                h1[m] = gelu_f(a);
            }
#pragma unroll
            for (int k = 0; k < KSLOT; k++) {
                float d = b2s[k];
#pragma unroll
                for (int m = 0; m < 10; m++) d += w2s[k * 10 + m] * h1[m];
                tb[k * 104 + c] = v[k] + d;
            }
        }
    }
    __syncthreads();

    for (int o = tid; o < 4000; o += 256) {
        int node = o / 500, r = o % 500;
        int k = r / 25, c4 = r - k * 25;
        *(float4*)(base + (node * KSLOT + k) * HID + c4 * 4) =
            *(const float4*)(t + node * 2080 + k * 104 + c4 * 4);
    }
}

// ---------------------------------------------------------------- K3: fused row mixer (tf32 mma, barrier-free)
// 64 rows/block, 128 threads = 4 independent warps; warp owns 16 rows end-to-end.
// Weights read directly from pre-permuted g_w1p/g_w2p (no smem staging, no __syncthreads).
#define SA 112    // Yn stride (112 mod 32 = 16 -> LDS.128 conflict-free)
#define SH 80     // Hs stride (64 + 16)
#define NCHUNK 7  // 448 = 7*64
#define MIX_SMEM ((64*SA + 64*SH) * 4)   // 49152 B -> 4 blocks/SM

__global__ __launch_bounds__(128, 4) void k_mixer(
    const float* __restrict__ lng, const float* __restrict__ lnb,
    const float* __restrict__ b1, const float* __restrict__ b2)
{
    extern __shared__ float smx[];
    float* Yn = smx;                  // [64][SA]  (per-warp 16-row regions)
    float* Hs = smx + 64 * SA;        // [64][SH]  (per-warp 16-row regions)

    int tid  = threadIdx.x;
    int warp = tid >> 5, lane = tid & 31;
    int q = lane >> 2, p = lane & 3;
    int m0 = warp * 16;
    size_t rowBase = (size_t)blockIdx.x * 64;

    // ---- rowLN -> Yn (tf32, perm16, zero-pad cols 100..111); own rows only ----
    for (int rr = 0; rr < 16; rr++) {
        int row = m0 + rr;
        const float* x = g_split + (rowBase + row) * HID;
        float v[4]; float s = 0.f, s2 = 0.f;
#pragma unroll
        for (int i = 0; i < 4; i++) {
            int c = lane + 32 * i;
            v[i] = (c < HID) ? x[c] : 0.f;
            s += v[i]; s2 += v[i] * v[i];
        }
#pragma unroll
        for (int off = 16; off; off >>= 1) {
            s  += __shfl_xor_sync(0xffffffffu, s,  off);
            s2 += __shfl_xor_sync(0xffffffffu, s2, off);
        }
        float mu = s * 0.01f;
        float rs = rsqrtf(s2 * 0.01f - mu * mu + LN_EPS);
#pragma unroll
        for (int i = 0; i < 4; i++) {
            int c = lane + 32 * i;
            if (c < HID)
                Yn[row * SA + kperm16(c)] =
                    f2tf_f((v[i] - mu) * rs * __ldg(lng + c) + __ldg(lnb + c));
        }
        if (lane < SA - HID) Yn[row * SA + kperm16(HID + lane)] = 0.f;
    }
    __syncwarp();

    float acc2[13][4];
#pragma unroll
    for (int i = 0; i < 13; i++)
#pragma unroll
        for (int j = 0; j < 4; j++) acc2[i][j] = 0.f;

    const float* ya = Yn + (m0 + q) * SA + 4 * p;
    const float* yb = Yn + (m0 + q + 8) * SA + 4 * p;
    const float* ha = Hs + (m0 + q) * SH + 4 * p;
    const float* hb = Hs + (m0 + q + 8) * SH + 4 * p;

#pragma unroll 1
    for (int ch = 0; ch < NCHUNK; ch++) {
        // ---- GEMM1 in two 32-wide n-halves: H[16 rows][64] ----
#pragma unroll
        for (int nh = 0; nh < 2; nh++) {
            float acc1[4][4];
#pragma unroll
            for (int nt = 0; nt < 4; nt++)
#pragma unroll
                for (int j = 0; j < 4; j++) acc1[nt][j] = 0.f;

            const float* w1c = g_w1p + (ch * 64 + nh * 32 + q) * SA + 4 * p;
#pragma unroll
            for (int ks = 0; ks < 7; ks++) {
                float4 a0 = *(const float4*)(ya + ks * 16);
                float4 a1 = *(const float4*)(yb + ks * 16);
#pragma unroll
                for (int nt = 0; nt < 4; nt++) {
                    float4 bv = *(const float4*)(w1c + nt * 8 * SA + ks * 16);
                    MMA_TF32(acc1[nt],
                             __float_as_uint(a0.x), __float_as_uint(a1.x),
                             __float_as_uint(a0.y), __float_as_uint(a1.y),
                             __float_as_uint(bv.x), __float_as_uint(bv.y));
                    MMA_TF32(acc1[nt],
                             __float_as_uint(a0.z), __float_as_uint(a1.z),
                             __float_as_uint(a0.w), __float_as_uint(a1.w),
                             __float_as_uint(bv.z), __float_as_uint(bv.w));
                }
            }

            // bias + gelu -> Hs (own rows)
#pragma unroll
            for (int nt = 0; nt < 4; nt++) {
                int cl0 = nh * 32 + nt * 8 + 2 * p;       // chunk-local col (even)
                int cg0 = ch * 64 + cl0;                  // global hidden col
                float bb0 = (cg0     < RH) ? __ldg(b1 + cg0)     : 0.f;
                float bb1 = (cg0 + 1 < RH) ? __ldg(b1 + cg0 + 1) : 0.f;
                int ps0 = kperm16(cl0), ps1 = kperm16(cl0 + 1);
                float* h0 = Hs + (m0 + q) * SH;
                float* h1 = Hs + (m0 + q + 8) * SH;
                h0[ps0] = f2tf_f(gelu_f(acc1[nt][0] + bb0));
                h0[ps1] = f2tf_f(gelu_f(acc1[nt][1] + bb1));
                h1[ps0] = f2tf_f(gelu_f(acc1[nt][2] + bb0));
                h1[ps1] = f2tf_f(gelu_f(acc1[nt][3] + bb1));
            }
        }
        __syncwarp();

        // ---- GEMM2: acc2[13 tiles] += H(16x64) @ W2chunk^T ----
        const float* w2c = g_w2p + (ch * 104 + q) * 64 + 4 * p;
#pragma unroll
        for (int ks = 0; ks < 4; ks++) {
            float4 a0 = *(const float4*)(ha + ks * 16);
            float4 a1 = *(const float4*)(hb + ks * 16);
#pragma unroll
            for (int nt = 0; nt < 13; nt++) {
                float4 bv = *(const float4*)(w2c + nt * 8 * 64 + ks * 16);
                MMA_TF32(acc2[nt],
                         __float_as_uint(a0.x), __float_as_uint(a1.x),
                         __float_as_uint(a0.y), __float_as_uint(a1.y),
                         __float_as_uint(bv.x), __float_as_uint(bv.y));
                MMA_TF32(acc2[nt],
                         __float_as_uint(a0.z), __float_as_uint(a1.z),
                         __float_as_uint(a0.w), __float_as_uint(a1.w),
                         __float_as_uint(bv.z), __float_as_uint(bv.w));
            }
        }
        __syncwarp();   // Hs reuse next chunk
    }

    // ---- epilogue: + b2 + residual -> g_y (fp32) ----
#pragma unroll
    for (int nt = 0; nt < 13; nt++) {
        int col = nt * 8 + 2 * p;
        if (col < HID) {
            float bb0 = __ldg(b2 + col), bb1 = __ldg(b2 + col + 1);
            size_t r0 = rowBase + m0 + q, r1 = r0 + 8;
            float2 x0 = *(const float2*)(g_split + r0 * HID + col);
            float2 x1 = *(const float2*)(g_split + r1 * HID + col);
            *(float2*)(g_y + r0 * HID + col) =
                make_float2(acc2[nt][0] + bb0 + x0.x, acc2[nt][1] + bb1 + x0.y);
            *(float2*)(g_y + r1 * HID + col) =
                make_float2(acc2[nt][2] + bb0 + x1.x, acc2[nt][3] + bb1 + x1.y);
        }
    }
}

// ---------------------------------------------------------------- K4: final LN + mean over K + out proj
__global__ __launch_bounds__(128) void k_final(
    const float* __restrict__ ng, const float* __restrict__ nb,
    const float* __restrict__ ow, const float* __restrict__ ob,
    float* __restrict__ out)
{
    __shared__ float Mp[4][HID];
    __shared__ float Ms[HID];
    int n = blockIdx.x;
    int tid = threadIdx.x, warp = tid >> 5, lane = tid & 31;

    float psum[4] = {0.f, 0.f, 0.f, 0.f};
    for (int rr = 0; rr < 5; rr++) {
        int k = warp * 5 + rr;
        const float* x = g_y + (size_t)(n * KSLOT + k) * HID;
        float v[4]; float s = 0.f, s2 = 0.f;
#pragma unroll
        for (int i = 0; i < 4; i++) {
            int c = lane + 32 * i;
            v[i] = (c < HID) ? x[c] : 0.f;
            s += v[i]; s2 += v[i] * v[i];
        }
#pragma unroll
        for (int off = 16; off; off >>= 1) {
            s  += __shfl_xor_sync(0xffffffffu, s,  off);
            s2 += __shfl_xor_sync(0xffffffffu, s2, off);
        }
        float mu = s * 0.01f;
        float rs = rsqrtf(s2 * 0.01f - mu * mu + LN_EPS);
#pragma unroll
        for (int i = 0; i < 4; i++) {
            int c = lane + 32 * i;
            if (c < HID) psum[i] += (v[i] - mu) * rs * ng[c] + nb[c];
        }
    }
#pragma unroll
    for (int i = 0; i < 4; i++) {
        int c = lane + 32 * i;
        if (c < HID) Mp[warp][c] = psum[i];
    }
    __syncthreads();
    if (tid < HID) Ms[tid] = (Mp[0][tid] + Mp[1][tid] + Mp[2][tid] + Mp[3][tid]) * (1.0f / KSLOT);
    __syncthreads();

    for (int o = warp; o < HID; o += 4) {
        float a = 0.f;
#pragma unroll
        for (int i = 0; i < 4; i++) {
            int c = lane + 32 * i;
            if (c < HID) a += Ms[c] * ow[o * HID + c];
        }
#pragma unroll
        for (int off = 16; off; off >>= 1) a += __shfl_xor_sync(0xffffffffu, a, off);
        if (lane == 0) out[(size_t)n * HID + o] = a + ob[o];
    }
}

// ---------------------------------------------------------------- launch
extern "C" void kernel_launch(void* const* d_in, const int* in_sizes, int n_in,
                              void* d_out, int out_size)
{
    const float* ef       = (const float*)d_in[0];
    const float* et       = (const float*)d_in[1];
    const int*   nid      = (const int*)  d_in[2];
    const int*   idx      = (const int*)  d_in[3];
    const float* lin_w    = (const float*)d_in[4];
    const float* lin_b    = (const float*)d_in[5];
    const float* col_ln_g = (const float*)d_in[6];
    const float* col_ln_b = (const float*)d_in[7];
    const float* col_w1   = (const float*)d_in[8];
    const float* col_b1   = (const float*)d_in[9];
    const float* col_w2   = (const float*)d_in[10];
    const float* col_b2   = (const float*)d_in[11];
    const float* row_ln_g = (const float*)d_in[12];
    const float* row_ln_b = (const float*)d_in[13];
    const float* row_w1   = (const float*)d_in[14];
    const float* row_b1   = (const float*)d_in[15];
    const float* row_w2   = (const float*)d_in[16];
    const float* row_b2   = (const float*)d_in[17];
    const float* norm_g   = (const float*)d_in[18];
    const float* norm_b   = (const float*)d_in[19];
    const float* out_w    = (const float*)d_in[20];
    const float* out_b    = (const float*)d_in[21];
    float* out = (float*)d_out;

    cudaFuncSetAttribute((const void*)k_edge,   cudaFuncAttributeMaxDynamicSharedMemorySize, EDGE_SMEM);
    cudaFuncSetAttribute((const void*)k_colmix, cudaFuncAttributeMaxDynamicSharedMemorySize, CMX_SMEM);
    cudaFuncSetAttribute((const void*)k_mixer,  cudaFuncAttributeMaxDynamicSharedMemorySize, MIX_SMEM);

    k_init<<<(MROWS * HID / 4 + 255) / 256, 256>>>(row_w1, row_w2, lin_w);
    k_edge<<<E_EDGES / 64, 256, EDGE_SMEM>>>(ef, et, nid, idx, lin_b);
    k_colmix<<<N_N / 8, 256, CMX_SMEM>>>(col_ln_g, col_ln_b, col_w1, col_b1, col_w2, col_b2);
    k_mixer<<<MROWS / 64, 128, MIX_SMEM>>>(row_ln_g, row_ln_b, row_b1, row_b2);
    k_final<<<N_N, 128>>>(norm_g, norm_b, out_w, out_b, out);
}

// round 11
// speedup vs baseline: 3.0953x; 1.0876x over previous
#include <cuda_runtime.h>
#include <cuda_bf16.h>
#include <math.h>

#define E_EDGES 200000
#define N_N     20000
#define KSLOT   20
#define HID     100
#define TDIM    100
#define EFD     128
#define FIN     228          // EFD + TDIM
#define RH      400
#define MROWS   (N_N*KSLOT)  // 400000
#define LN_EPS  1e-5f

// scratch (device globals; no allocation allowed)
__device__ float g_split[(size_t)MROWS * HID];  // x: scatter target, colmix in-place, residual
__device__ float g_y[(size_t)MROWS * HID];      // mixer output X2
__device__ float g_w1p[448 * 112];              // tf32+perm16 W1 [448][112]
__device__ float g_w2p[7 * 104 * 64];           // tf32+perm16 W2 chunks [7][104][64]
__device__ float g_wep[112 * 240];              // tf32+perm16 edge W [112][240]
__device__ float g_tw[128];                     // time-encode freqs (padded)

__device__ __forceinline__ float gelu_f(float x) {
    return 0.5f * x * (1.0f + erff(x * 0.70710678118654752f));
}

__device__ __forceinline__ unsigned f2tf(float v) {
    unsigned r;
    asm("cvt.rna.tf32.f32 %0, %1;" : "=r"(r) : "f"(v));
    return r;
}
__device__ __forceinline__ float f2tf_f(float v) { return __uint_as_float(f2tf(v)); }

// permute k within each 16-block: thread p's 4 frag elems (k = p, p+4, p+8, p+12) contiguous
__device__ __forceinline__ int kperm16(int k) {
    return (k & ~15) | (((k & 3) << 2) | ((k >> 2) & 3));
}

__device__ __forceinline__ void barpair(int id) {
    asm volatile("bar.sync %0, 64;" :: "r"(id) : "memory");
}

#define MMA_TF32(c,a0,a1,a2,a3,b0,b1) \
    asm volatile("mma.sync.aligned.m16n8k8.row.col.f32.tf32.tf32.f32 " \
        "{%0,%1,%2,%3}, {%4,%5,%6,%7}, {%8,%9}, {%0,%1,%2,%3};" \
        : "+f"(c[0]),"+f"(c[1]),"+f"(c[2]),"+f"(c[3]) \
        : "r"(a0),"r"(a1),"r"(a2),"r"(a3),"r"(b0),"r"(b1))

// ---------------------------------------------------------------- K0: init (zero split + all weight prep)
__global__ void k_init(const float* __restrict__ w1, const float* __restrict__ w2,
                       const float* __restrict__ lw) {
    int i = blockIdx.x * 256 + threadIdx.x;
    const int n4 = MROWS * HID / 4;            // 10,000,000
    if (i < n4) ((float4*)g_split)[i] = make_float4(0.f, 0.f, 0.f, 0.f);
    if (i < 448 * 112) {
        int ng = i / 112, k = i - ng * 112;
        g_w1p[ng * 112 + kperm16(k)] =
            f2tf_f((ng < RH && k < HID) ? w1[ng * HID + k] : 0.f);
    }
    if (i < 7 * 104 * 64) {
        int ch = i / (104 * 64);
        int r  = i - ch * 104 * 64;
        int n  = r >> 6, k = r & 63;
        g_w2p[(ch * 104 + n) * 64 + kperm16(k)] =
            f2tf_f((n < HID) ? w2[n * RH + ch * 64 + k] : 0.f);
    }
    if (i < 112 * 240) {
        int n = i / 240, k = i - n * 240;
        g_wep[n * 240 + kperm16(k)] =
            f2tf_f((n < HID && k < FIN) ? lw[n * FIN + k] : 0.f);
    }
    if (i < 128) g_tw[i] = (i < TDIM) ? exp10f(-(9.0f / 99.0f) * (float)i) : 0.f;
}

// ---------------------------------------------------------------- K1: edge MLP (tf32 mma) + scatter
// 64 edges/block, 256 threads = 8 warps = 4 m-groups (16 edges) x 2 n-halves.
#define ESA 240          // fs stride (240 mod 32 = 16 -> LDS.128 conflict-free)
#define EDGE_SMEM (64 * ESA * 4)   // 61440 B -> 2 blocks/SM

__global__ __launch_bounds__(256, 2) void k_edge(
    const float* __restrict__ ef, const float* __restrict__ et,
    const int* __restrict__ nid, const int* __restrict__ idxp,
    const float* __restrict__ lb)
{
    extern __shared__ float fs[];    // [64][240] tf32, perm16
    int tid = threadIdx.x;
    int e0 = blockIdx.x * 64;

    for (int o = tid; o < 64 * 32; o += 256) {
        int e = o >> 5, j4 = o & 31;
        float4 v = ((const float4*)ef)[(size_t)(e0 + e) * 32 + j4];
        float* dst = fs + e * ESA;
        int k0 = j4 * 4;
        dst[kperm16(k0)]     = f2tf_f(v.x);
        dst[kperm16(k0 + 1)] = f2tf_f(v.y);
        dst[kperm16(k0 + 2)] = f2tf_f(v.z);
        dst[kperm16(k0 + 3)] = f2tf_f(v.w);
    }
    for (int o = tid; o < 64 * 112; o += 256) {
        int e = o / 112, tt = o - e * 112;
        float val = 0.f;
        if (tt < TDIM) val = __cosf(et[e0 + e] * __ldg(g_tw + tt));
        fs[e * ESA + kperm16(128 + tt)] = f2tf_f(val);
    }
    __syncthreads();

    int warp = tid >> 5, lane = tid & 31;
    int q = lane >> 2, p = lane & 3;
    int mgrp = warp & 3, h = warp >> 2;
    int m0 = mgrp * 16;

    float acc[7][4];
#pragma unroll
    for (int i = 0; i < 7; i++)
#pragma unroll
        for (int j = 0; j < 4; j++) acc[i][j] = 0.f;

#pragma unroll
    for (int ks = 0; ks < 15; ks++) {          // 15 x k16 over K=240
        float4 a0 = *(const float4*)(fs + (m0 + q) * ESA + ks * 16 + 4 * p);
        float4 a1 = *(const float4*)(fs + (m0 + q + 8) * ESA + ks * 16 + 4 * p);
#pragma unroll
        for (int nt = 0; nt < 7; nt++) {
            float4 bv = *(const float4*)(g_wep + ((h * 7 + nt) * 8 + q) * ESA + ks * 16 + 4 * p);
            MMA_TF32(acc[nt],
                     __float_as_uint(a0.x), __float_as_uint(a1.x),
                     __float_as_uint(a0.y), __float_as_uint(a1.y),
                     __float_as_uint(bv.x), __float_as_uint(bv.y));
            MMA_TF32(acc[nt],
                     __float_as_uint(a0.z), __float_as_uint(a1.z),
                     __float_as_uint(a0.w), __float_as_uint(a1.w),
                     __float_as_uint(bv.z), __float_as_uint(bv.w));
        }
    }

    int e1 = e0 + m0 + q, e2 = e1 + 8;
    int pos1 = nid[e1] * KSLOT + idxp[e1];
    int pos2 = nid[e2] * KSLOT + idxp[e2];
#pragma unroll
    for (int nt = 0; nt < 7; nt++) {
        int col = (h * 7 + nt) * 8 + 2 * p;
        if (col < HID) {
            float b0 = __ldg(lb + col), b1 = __ldg(lb + col + 1);
            *(float2*)(g_split + (size_t)pos1 * HID + col) =
                make_float2(acc[nt][0] + b0, acc[nt][1] + b1);
            *(float2*)(g_split + (size_t)pos2 * HID + col) =
                make_float2(acc[nt][2] + b0, acc[nt][3] + b1);
        }
    }
}

// ---------------------------------------------------------------- K2: column mixer v3 (8 nodes/block)
#define CMX_SMEM ((8 * 2080 + 512) * 4)

__global__ __launch_bounds__(256) void k_colmix(
    const float* __restrict__ cg, const float* __restrict__ cb,
    const float* __restrict__ cw1, const float* __restrict__ cb1,
    const float* __restrict__ cw2, const float* __restrict__ cb2)
{
    extern __shared__ float sm2[];
    float* t   = sm2;                  // 8 nodes x [20][104]
    float* w1s = sm2 + 8 * 2080;       // [200]
    float* w2s = w1s + 200;            // [200]
    float* gs  = w2s + 200;            // [20]
    float* bs  = gs + 20;              // [20]
    float* b1s = bs + 20;              // [10]
    float* b2s = b1s + 10;             // [20]
    int tid = threadIdx.x;
    float* base = g_split + (size_t)blockIdx.x * 8 * KSLOT * HID;

    for (int o = tid; o < 200; o += 256) { w1s[o] = cw1[o]; w2s[o] = cw2[o]; }
    if (tid < 20) { gs[tid] = cg[tid]; bs[tid] = cb[tid]; b2s[tid] = cb2[tid]; }
    if (tid >= 32 && tid < 42) b1s[tid - 32] = cb1[tid - 32];

    for (int o = tid; o < 4000; o += 256) {
        int node = o / 500, r = o % 500;
        int k = r / 25, c4 = r - k * 25;
        *(float4*)(t + node * 2080 + k * 104 + c4 * 4) =
            *(const float4*)(base + (node * KSLOT + k) * HID + c4 * 4);
    }
    __syncthreads();

    int node = tid >> 5, lane = tid & 31;
    float* tb = t + node * 2080;
#pragma unroll
    for (int i = 0; i < 4; i++) {
        int c = lane + 32 * i;
        if (c < HID) {
            float v[KSLOT]; float s = 0.f;
#pragma unroll
            for (int k = 0; k < KSLOT; k++) { v[k] = tb[k * 104 + c]; s += v[k]; }
            float mu = s * (1.0f / KSLOT);
            float s2 = 0.f;
#pragma unroll
            for (int k = 0; k < KSLOT; k++) { float d = v[k] - mu; s2 += d * d; }
            float rs = rsqrtf(s2 * (1.0f / KSLOT) + LN_EPS);

            float vn[KSLOT];
#pragma unroll
            for (int k = 0; k < KSLOT; k++) vn[k] = (v[k] - mu) * rs * gs[k] + bs[k];

            float h1[10];
#pragma unroll
            for (int m = 0; m < 10; m++) {
                float a = b1s[m];
#pragma unroll
                for (int k = 0; k < KSLOT; k++) a += w1s[m * KSLOT + k] * vn[k];
                h1[m] = gelu_f(a);
            }
#pragma unroll
            for (int k = 0; k < KSLOT; k++) {
                float d = b2s[k];
#pragma unroll
                for (int m = 0; m < 10; m++) d += w2s[k * 10 + m] * h1[m];
                tb[k * 104 + c] = v[k] + d;
            }
        }
    }
    __syncthreads();

    for (int o = tid; o < 4000; o += 256) {
        int node = o / 500, r = o % 500;
        int k = r / 25, c4 = r - k * 25;
        *(float4*)(base + (node * KSLOT + k) * HID + c4 * 4) =
            *(const float4*)(t + node * 2080 + k * 104 + c4 * 4);
    }
}

// ---------------------------------------------------------------- K3: fused row mixer (tf32 mma, warp-pair cooperative)
// 64 rows/block, 128 threads = 2 pairs; pair owns 32 rows, warps split n-dim.
// Weights via LDG from pre-permuted g_w1p/g_w2p; pair syncs via named bar.sync(64).
#define SA 112    // Yn stride (112 mod 32 = 16 -> LDS.128 conflict-free)
#define SH 80     // Hs stride (64 + 16)
#define NCHUNK 7  // 448 = 7*64
#define MIX_SMEM ((64*SA + 64*SH) * 4)   // 49152 B -> 4 blocks/SM

__global__ __launch_bounds__(128, 4) void k_mixer(
    const float* __restrict__ lng, const float* __restrict__ lnb,
    const float* __restrict__ b1, const float* __restrict__ b2)
{
    extern __shared__ float smx[];
    float* Yn = smx;                  // [64][SA]  (per-pair 32-row regions)
    float* Hs = smx + 64 * SA;        // [64][SH]

    int tid  = threadIdx.x;
    int warp = tid >> 5, lane = tid & 31;
    int q = lane >> 2, p = lane & 3;
    int pair = warp >> 1;             // 0,1
    int h    = warp & 1;              // n-half within pair
    int m0   = pair * 32;
    int barid = pair + 1;
    size_t rowBase = (size_t)blockIdx.x * 64;

    // ---- rowLN -> Yn: each warp does 16 rows (warp*16 covers pair's 32 rows) ----
    for (int rr = 0; rr < 16; rr++) {
        int row = warp * 16 + rr;
        const float* x = g_split + (rowBase + row) * HID;
        float v[4]; float s = 0.f, s2 = 0.f;
#pragma unroll
        for (int i = 0; i < 4; i++) {
            int c = lane + 32 * i;
            v[i] = (c < HID) ? x[c] : 0.f;
            s += v[i]; s2 += v[i] * v[i];
        }
#pragma unroll
        for (int off = 16; off; off >>= 1) {
            s  += __shfl_xor_sync(0xffffffffu, s,  off);
            s2 += __shfl_xor_sync(0xffffffffu, s2, off);
        }
        float mu = s * 0.01f;
        float rs = rsqrtf(s2 * 0.01f - mu * mu + LN_EPS);
#pragma unroll
        for (int i = 0; i < 4; i++) {
            int c = lane + 32 * i;
            if (c < HID)
                Yn[row * SA + kperm16(c)] =
                    f2tf_f((v[i] - mu) * rs * __ldg(lng + c) + __ldg(lnb + c));
        }
        if (lane < SA - HID) Yn[row * SA + kperm16(HID + lane)] = 0.f;
    }
    barpair(barid);   // pair's Yn complete

    float acc2[2][7][4];
#pragma unroll
    for (int mt = 0; mt < 2; mt++)
#pragma unroll
        for (int i = 0; i < 7; i++)
#pragma unroll
            for (int j = 0; j < 4; j++) acc2[mt][i][j] = 0.f;

    const float* ya0 = Yn + (m0 + q) * SA + 4 * p;       // mt0 rows
    const float* ya1 = Yn + (m0 + 16 + q) * SA + 4 * p;  // mt1 rows
    const float* ha0 = Hs + (m0 + q) * SH + 4 * p;
    const float* ha1 = Hs + (m0 + 16 + q) * SH + 4 * p;

#pragma unroll 1
    for (int ch = 0; ch < NCHUNK; ch++) {
        // ---- GEMM1: this warp's 32-col half, all 32 rows ----
        float acc1[2][4][4];
#pragma unroll
        for (int mt = 0; mt < 2; mt++)
#pragma unroll
            for (int nt = 0; nt < 4; nt++)
#pragma unroll
                for (int j = 0; j < 4; j++) acc1[mt][nt][j] = 0.f;

        const float* w1c = g_w1p + (ch * 64 + h * 32 + q) * SA + 4 * p;
#pragma unroll
        for (int ks = 0; ks < 7; ks++) {
            float4 a00 = *(const float4*)(ya0 + ks * 16);
            float4 a01 = *(const float4*)(ya0 + 8 * SA + ks * 16);
            float4 a10 = *(const float4*)(ya1 + ks * 16);
            float4 a11 = *(const float4*)(ya1 + 8 * SA + ks * 16);
#pragma unroll
            for (int nt = 0; nt < 4; nt++) {
                float4 bv = *(const float4*)(w1c + nt * 8 * SA + ks * 16);
                MMA_TF32(acc1[0][nt],
                         __float_as_uint(a00.x), __float_as_uint(a01.x),
                         __float_as_uint(a00.y), __float_as_uint(a01.y),
                         __float_as_uint(bv.x), __float_as_uint(bv.y));
                MMA_TF32(acc1[0][nt],
                         __float_as_uint(a00.z), __float_as_uint(a01.z),
                         __float_as_uint(a00.w), __float_as_uint(a01.w),
                         __float_as_uint(bv.z), __float_as_uint(bv.w));
                MMA_TF32(acc1[1][nt],
                         __float_as_uint(a10.x), __float_as_uint(a11.x),
                         __float_as_uint(a10.y), __float_as_uint(a11.y),
                         __float_as_uint(bv.x), __float_as_uint(bv.y));
                MMA_TF32(acc1[1][nt],
                         __float_as_uint(a10.z), __float_as_uint(a11.z),
                         __float_as_uint(a10.w), __float_as_uint(a11.w),
                         __float_as_uint(bv.z), __float_as_uint(bv.w));
            }
        }

        barpair(barid);   // partner's GEMM2 reads of prev Hs complete

        // ---- bias + gelu -> Hs (this warp's cols, both m-tiles) ----
#pragma unroll
        for (int nt = 0; nt < 4; nt++) {
            int cl0 = h * 32 + nt * 8 + 2 * p;
            int cg0 = ch * 64 + cl0;
            float bb0 = (cg0     < RH) ? __ldg(b1 + cg0)     : 0.f;
            float bb1 = (cg0 + 1 < RH) ? __ldg(b1 + cg0 + 1) : 0.f;
            int ps0 = kperm16(cl0), ps1 = kperm16(cl0 + 1);
#pragma unroll
            for (int mt = 0; mt < 2; mt++) {
                float* h0 = Hs + (m0 + mt * 16 + q) * SH;
                float* h1 = Hs + (m0 + mt * 16 + q + 8) * SH;
                h0[ps0] = f2tf_f(gelu_f(acc1[mt][nt][0] + bb0));
                h0[ps1] = f2tf_f(gelu_f(acc1[mt][nt][1] + bb1));
                h1[ps0] = f2tf_f(gelu_f(acc1[mt][nt][2] + bb0));
                h1[ps1] = f2tf_f(gelu_f(acc1[mt][nt][3] + bb1));
            }
        }

        barpair(barid);   // pair's H complete

        // ---- GEMM2: this warp's output tiles (h=0: 0..6, h=1: 7..12), 32 rows ----
        const float* w2c = g_w2p + (ch * 104 + h * 56 + q) * 64 + 4 * p;
#pragma unroll
        for (int ks = 0; ks < 4; ks++) {
            float4 a00 = *(const float4*)(ha0 + ks * 16);
            float4 a01 = *(const float4*)(ha0 + 8 * SH + ks * 16);
            float4 a10 = *(const float4*)(ha1 + ks * 16);
            float4 a11 = *(const float4*)(ha1 + 8 * SH + ks * 16);
#pragma unroll
            for (int nt = 0; nt < 7; nt++) {
                if (nt < 7 - h) {
                    float4 bv = *(const float4*)(w2c + nt * 8 * 64 + ks * 16);
                    MMA_TF32(acc2[0][nt],
                             __float_as_uint(a00.x), __float_as_uint(a01.x),
                             __float_as_uint(a00.y), __float_as_uint(a01.y),
                             __float_as_uint(bv.x), __float_as_uint(bv.y));
                    MMA_TF32(acc2[0][nt],
                             __float_as_uint(a00.z), __float_as_uint(a01.z),
                             __float_as_uint(a00.w), __float_as_uint(a01.w),
                             __float_as_uint(bv.z), __float_as_uint(bv.w));
                    MMA_TF32(acc2[1][nt],
                             __float_as_uint(a10.x), __float_as_uint(a11.x),
                             __float_as_uint(a10.y), __float_as_uint(a11.y),
                             __float_as_uint(bv.x), __float_as_uint(bv.y));
                    MMA_TF32(acc2[1][nt],
                             __float_as_uint(a10.z), __float_as_uint(a11.z),
                             __float_as_uint(a10.w), __float_as_uint(a11.w),
                             __float_as_uint(bv.z), __float_as_uint(bv.w));
                }
            }
        }
    }

    // ---- epilogue: + b2 + residual -> g_y (fp32), 32 rows, this warp's cols ----
#pragma unroll
    for (int nt = 0; nt < 7; nt++) {
        if (nt < 7 - h) {
            int col = (h * 7 + nt) * 8 + 2 * p;
            if (col < HID) {
                float bb0 = __ldg(b2 + col), bb1 = __ldg(b2 + col + 1);
#pragma unroll
                for (int mt = 0; mt < 2; mt++) {
                    size_t r0 = rowBase + m0 + mt * 16 + q, r1 = r0 + 8;
                    float2 x0 = *(const float2*)(g_split + r0 * HID + col);
                    float2 x1 = *(const float2*)(g_split + r1 * HID + col);
                    *(float2*)(g_y + r0 * HID + col) =
                        make_float2(acc2[mt][nt][0] + bb0 + x0.x, acc2[mt][nt][1] + bb1 + x0.y);
                    *(float2*)(g_y + r1 * HID + col) =
                        make_float2(acc2[mt][nt][2] + bb0 + x1.x, acc2[mt][nt][3] + bb1 + x1.y);
                }
            }
        }
    }
}

// ---------------------------------------------------------------- K4: final LN + mean over K + out proj
__global__ __launch_bounds__(128) void k_final(
    const float* __restrict__ ng, const float* __restrict__ nb,
    const float* __restrict__ ow, const float* __restrict__ ob,
    float* __restrict__ out)
{
    __shared__ float Mp[4][HID];
    __shared__ float Ms[HID];
    int n = blockIdx.x;
    int tid = threadIdx.x, warp = tid >> 5, lane = tid & 31;

    float psum[4] = {0.f, 0.f, 0.f, 0.f};
    for (int rr = 0; rr < 5; rr++) {
        int k = warp * 5 + rr;
        const float* x = g_y + (size_t)(n * KSLOT + k) * HID;
        float v[4]; float s = 0.f, s2 = 0.f;
#pragma unroll
        for (int i = 0; i < 4; i++) {
            int c = lane + 32 * i;
            v[i] = (c < HID) ? x[c] : 0.f;
            s += v[i]; s2 += v[i] * v[i];
        }
#pragma unroll
        for (int off = 16; off; off >>= 1) {
            s  += __shfl_xor_sync(0xffffffffu, s,  off);
            s2 += __shfl_xor_sync(0xffffffffu, s2, off);
        }
        float mu = s * 0.01f;
        float rs = rsqrtf(s2 * 0.01f - mu * mu + LN_EPS);
#pragma unroll
        for (int i = 0; i < 4; i++) {
            int c = lane + 32 * i;
            if (c < HID) psum[i] += (v[i] - mu) * rs * ng[c] + nb[c];
        }
    }
#pragma unroll
    for (int i = 0; i < 4; i++) {
        int c = lane + 32 * i;
        if (c < HID) Mp[warp][c] = psum[i];
    }
    __syncthreads();
    if (tid < HID) Ms[tid] = (Mp[0][tid] + Mp[1][tid] + Mp[2][tid] + Mp[3][tid]) * (1.0f / KSLOT);
    __syncthreads();

    for (int o = warp; o < HID; o += 4) {
        float a = 0.f;
#pragma unroll
        for (int i = 0; i < 4; i++) {
            int c = lane + 32 * i;
            if (c < HID) a += Ms[c] * ow[o * HID + c];
        }
#pragma unroll
        for (int off = 16; off; off >>= 1) a += __shfl_xor_sync(0xffffffffu, a, off);
        if (lane == 0) out[(size_t)n * HID + o] = a + ob[o];
    }
}

// ---------------------------------------------------------------- launch
extern "C" void kernel_launch(void* const* d_in, const int* in_sizes, int n_in,
                              void* d_out, int out_size)
{
    const float* ef       = (const float*)d_in[0];
    const float* et       = (const float*)d_in[1];
    const int*   nid      = (const int*)  d_in[2];
    const int*   idx      = (const int*)  d_in[3];
    const float* lin_w    = (const float*)d_in[4];
    const float* lin_b    = (const float*)d_in[5];
    const float* col_ln_g = (const float*)d_in[6];
    const float* col_ln_b = (const float*)d_in[7];
    const float* col_w1   = (const float*)d_in[8];
    const float* col_b1   = (const float*)d_in[9];
    const float* col_w2   = (const float*)d_in[10];
    const float* col_b2   = (const float*)d_in[11];
    const float* row_ln_g = (const float*)d_in[12];
    const float* row_ln_b = (const float*)d_in[13];
    const float* row_w1   = (const float*)d_in[14];
    const float* row_b1   = (const float*)d_in[15];
    const float* row_w2   = (const float*)d_in[16];
    const float* row_b2   = (const float*)d_in[17];
    const float* norm_g   = (const float*)d_in[18];
    const float* norm_b   = (const float*)d_in[19];
    const float* out_w    = (const float*)d_in[20];
    const float* out_b    = (const float*)d_in[21];
    float* out = (float*)d_out;

    cudaFuncSetAttribute((const void*)k_edge,   cudaFuncAttributeMaxDynamicSharedMemorySize, EDGE_SMEM);
    cudaFuncSetAttribute((const void*)k_colmix, cudaFuncAttributeMaxDynamicSharedMemorySize, CMX_SMEM);
    cudaFuncSetAttribute((const void*)k_mixer,  cudaFuncAttributeMaxDynamicSharedMemorySize, MIX_SMEM);

    k_init<<<(MROWS * HID / 4 + 255) / 256, 256>>>(row_w1, row_w2, lin_w);
    k_edge<<<E_EDGES / 64, 256, EDGE_SMEM>>>(ef, et, nid, idx, lin_b);
    k_colmix<<<N_N / 8, 256, CMX_SMEM>>>(col_ln_g, col_ln_b, col_w1, col_b1, col_w2, col_b2);
    k_mixer<<<MROWS / 64, 128, MIX_SMEM>>>(row_ln_g, row_ln_b, row_b1, row_b2);
    k_final<<<N_N, 128>>>(norm_g, norm_b, out_w, out_b, out);
}